// round 3
// baseline (speedup 1.0000x reference)
#include <cuda_runtime.h>
#include <math.h>

#define BATCH   8
#define NTOT    4097
#define NR      4096
#define DPT     61
#define NP      1024
#define NS      16
#define CH      128
#define EPSV    1e-5f
#define OXYZ    (BATCH*1025*3)   // offset of out_pts in flattened output

// ----------------------------- device scratch ------------------------------
__device__ float g_pnorm[BATCH * NR];
__device__ int   g_fid[BATCH * NP];
__device__ float g_newxyz[BATCH * NP * 3];
__device__ int   g_knn[BATCH * NP * NS];
__device__ float g_y0[(size_t)BATCH * NP * NS * CH];   // 64 MB
__device__ float g_w0t[64 * CH];                        // [cin][cout]
__device__ float g_w1t[CH * CH];                        // [cin][cout]
__device__ float g_A0[CH], g_B0[CH], g_A1[CH], g_B1[CH];

// ---------------------------------------------------------------------------
// prep: transpose SA weights, fold BN:  bn(Wx+b) = (Wx)*A + B
//   A = g/sqrt(v+eps),  B = (b-m)*A + bt
// ---------------------------------------------------------------------------
__global__ void prep_kernel(const float* __restrict__ w0, const float* __restrict__ b0,
                            const float* __restrict__ g0, const float* __restrict__ bt0,
                            const float* __restrict__ m0, const float* __restrict__ v0,
                            const float* __restrict__ w1, const float* __restrict__ b1,
                            const float* __restrict__ g1, const float* __restrict__ bt1,
                            const float* __restrict__ m1, const float* __restrict__ v1) {
    int t = threadIdx.x;
    for (int i = t; i < 64 * CH; i += 256) {
        int c = i >> 7, o = i & 127;
        g_w0t[i] = w0[o * 64 + c];
    }
    for (int i = t; i < CH * CH; i += 256) {
        int c = i >> 7, o = i & 127;
        g_w1t[i] = w1[o * CH + c];
    }
    if (t < CH) {
        float a0 = g0[t] / sqrtf(v0[t] + EPSV);
        g_A0[t] = a0;
        g_B0[t] = (b0[t] - m0[t]) * a0 + bt0[t];
        float a1 = g1[t] / sqrtf(v1[t] + EPSV);
        g_A1[t] = a1;
        g_B1[t] = (b1[t] - m1[t]) * a1 + bt1[t];
    }
}

// ---------------------------------------------------------------------------
// pnorm: |p|^2 for every real point, association ((x*x+y*y)+z*z), no FMA
// ---------------------------------------------------------------------------
__global__ void pnorm_kernel(const float* __restrict__ xyz) {
    int i = blockIdx.x * 256 + threadIdx.x;
    if (i < BATCH * NR) {
        int b = i >> 12, p = i & 4095;
        const float* q = xyz + ((size_t)b * NTOT + 1 + p) * 3;
        float x = q[0], y = q[1], z = q[2];
        g_pnorm[i] = __fadd_rn(__fadd_rn(__fmul_rn(x, x), __fmul_rn(y, y)), __fmul_rn(z, z));
    }
}

// ---------------------------------------------------------------------------
// FPS: one CTA per batch, 1024 threads * 4 points (registers).
// Exactly replicates: dist=min(dist, |p-c|^2); far=argmax(dist) (first-index).
// ---------------------------------------------------------------------------
__global__ void __launch_bounds__(1024) fps_kernel(const float* __restrict__ xyz) {
    int b = blockIdx.x;
    int tid = threadIdx.x;
    const float* base = xyz + ((size_t)b * NTOT + 1) * 3;

    float px[4], py[4], pz[4], dd[4];
#pragma unroll
    for (int i = 0; i < 4; i++) {
        int p = tid * 4 + i;
        px[i] = base[p * 3 + 0];
        py[i] = base[p * 3 + 1];
        pz[i] = base[p * 3 + 2];
        dd[i] = 1e10f;
    }

    __shared__ float s_val[32];
    __shared__ int   s_idx[32];
    __shared__ float s_c[3];
    __shared__ int   s_far;
    if (tid == 0) { s_c[0] = base[0]; s_c[1] = base[1]; s_c[2] = base[2]; s_far = 0; }
    __syncthreads();

    for (int it = 0; it < NP; it++) {
        if (tid == 0) g_fid[b * NP + it] = s_far;
        float cx = s_c[0], cy = s_c[1], cz = s_c[2];

        float bv = -1.0f; int bi = 0;
#pragma unroll
        for (int i = 0; i < 4; i++) {
            float dx = __fsub_rn(px[i], cx);
            float dy = __fsub_rn(py[i], cy);
            float dz = __fsub_rn(pz[i], cz);
            float d = __fadd_rn(__fadd_rn(__fmul_rn(dx, dx), __fmul_rn(dy, dy)),
                                __fmul_rn(dz, dz));
            dd[i] = fminf(dd[i], d);
            int pidx = tid * 4 + i;
            if (dd[i] > bv || (dd[i] == bv && pidx < bi)) { bv = dd[i]; bi = pidx; }
        }
        // warp reduce (lexicographic max on (val, -idx))
#pragma unroll
        for (int o = 16; o > 0; o >>= 1) {
            float ov = __shfl_down_sync(0xffffffffu, bv, o);
            int   oi = __shfl_down_sync(0xffffffffu, bi, o);
            if (ov > bv || (ov == bv && oi < bi)) { bv = ov; bi = oi; }
        }
        if ((tid & 31) == 0) { s_val[tid >> 5] = bv; s_idx[tid >> 5] = bi; }
        __syncthreads();
        if (tid < 32) {
            bv = s_val[tid]; bi = s_idx[tid];
#pragma unroll
            for (int o = 16; o > 0; o >>= 1) {
                float ov = __shfl_down_sync(0xffffffffu, bv, o);
                int   oi = __shfl_down_sync(0xffffffffu, bi, o);
                if (ov > bv || (ov == bv && oi < bi)) { bv = ov; bi = oi; }
            }
            if (tid == 0) s_far = bi;
        }
        __syncthreads();
        int nf = s_far;
        if ((nf >> 2) == tid) {
            int i = nf & 3;
            s_c[0] = px[i]; s_c[1] = py[i]; s_c[2] = pz[i];
        }
        __syncthreads();
    }
}

// ---------------------------------------------------------------------------
// new_xyz gather + out_xyz write (rows 0..1024 per batch)
// ---------------------------------------------------------------------------
__global__ void newxyz_kernel(const float* __restrict__ xyz, float* __restrict__ out) {
    int i = blockIdx.x * 256 + threadIdx.x;
    if (i < BATCH * NP) {
        int b = i >> 10, s = i & 1023;
        int f = g_fid[i];
        const float* q = xyz + ((size_t)b * NTOT + 1 + f) * 3;
        float x = q[0], y = q[1], z = q[2];
        g_newxyz[i * 3 + 0] = x;
        g_newxyz[i * 3 + 1] = y;
        g_newxyz[i * 3 + 2] = z;
        float* o = out + ((size_t)b * 1025 + 1 + s) * 3;
        o[0] = x; o[1] = y; o[2] = z;
        if (s == 0) {
            const float* c = xyz + (size_t)b * NTOT * 3;
            float* oc = out + (size_t)b * 1025 * 3;
            oc[0] = c[0]; oc[1] = c[1]; oc[2] = c[2];
        }
    }
}

// ---------------------------------------------------------------------------
// kNN-16: 128 queries/CTA, candidate tiles in smem, per-thread heap in smem.
// d2 = (qn + pn) - 2*dot, same association as reference; stable top_k set via
// strict-less insert + lexicographic-max eviction.
// ---------------------------------------------------------------------------
#define KTILE 512
__global__ void __launch_bounds__(128) knn_kernel(const float* __restrict__ xyz) {
    __shared__ float tx_[KTILE], ty_[KTILE], tz_[KTILE], tn_[KTILE];
    __shared__ float hv[16][128];
    __shared__ int   hi[16][128];

    int b  = blockIdx.x >> 3;
    int qt = blockIdx.x & 7;
    int t  = threadIdx.x;
    int s  = qt * 128 + t;
    int srow = b * NP + s;

    float qx = g_newxyz[srow * 3 + 0];
    float qy = g_newxyz[srow * 3 + 1];
    float qz = g_newxyz[srow * 3 + 2];
    float qn = __fadd_rn(__fadd_rn(__fmul_rn(qx, qx), __fmul_rn(qy, qy)), __fmul_rn(qz, qz));

    const float INF = __int_as_float(0x7f800000);
#pragma unroll
    for (int k = 0; k < 16; k++) { hv[k][t] = INF; hi[k][t] = 0x7fffffff; }
    float wv = INF; int ws = 0;

    const float* base = xyz + ((size_t)b * NTOT + 1) * 3;
    for (int tile = 0; tile < NR; tile += KTILE) {
        __syncthreads();
        for (int e = t; e < KTILE; e += 128) {
            int p = tile + e;
            tx_[e] = base[p * 3 + 0];
            ty_[e] = base[p * 3 + 1];
            tz_[e] = base[p * 3 + 2];
            tn_[e] = g_pnorm[b * NR + p];
        }
        __syncthreads();
        for (int j = 0; j < KTILE; j++) {
            float dot = __fadd_rn(__fadd_rn(__fmul_rn(qx, tx_[j]), __fmul_rn(qy, ty_[j])),
                                  __fmul_rn(qz, tz_[j]));
            float d2 = __fsub_rn(__fadd_rn(qn, tn_[j]), __fmul_rn(2.0f, dot));
            if (d2 < wv) {
                hv[ws][t] = d2; hi[ws][t] = tile + j;
                float nwv = hv[0][t]; int nws = 0; int nwi = hi[0][t];
#pragma unroll
                for (int k = 1; k < 16; k++) {
                    float v = hv[k][t]; int ii = hi[k][t];
                    if (v > nwv || (v == nwv && ii > nwi)) { nwv = v; nws = k; nwi = ii; }
                }
                wv = nwv; ws = nws;
            }
        }
    }
#pragma unroll
    for (int k = 0; k < 16; k++) g_knn[(size_t)srow * NS + k] = hi[k][t];
}

// ---------------------------------------------------------------------------
// Layer 0: gathered feat(64) @ W0t -> bn+relu -> g_y0.  Tile 128x128, K=64.
// 256 threads, 8x8 micro-tile. Rows = 8 samples * 16 neighbors.
// ---------------------------------------------------------------------------
__global__ void __launch_bounds__(256) l0_kernel(const float* __restrict__ xyz,
                                                 const float* __restrict__ points) {
    __shared__ __align__(16) float As[32][133];
    __shared__ __align__(16) float Bs[32][132];
    __shared__ int   s_n[128];
    __shared__ float s_nx[8][3];

    int ct = blockIdx.x;
    int sbase = ct * 8;               // global sample index base (b*1024+s)
    int b = sbase >> 10;
    int t = threadIdx.x;
    int tx = t & 15, ty = t >> 4;

    if (t < 128) s_n[t] = g_knn[(size_t)(sbase + (t >> 4)) * NS + (t & 15)];
    if (t < 24)  s_nx[t / 3][t % 3] = g_newxyz[(sbase + t / 3) * 3 + (t % 3)];
    __syncthreads();

    float acc[8][8];
#pragma unroll
    for (int i = 0; i < 8; i++)
#pragma unroll
        for (int j = 0; j < 8; j++) acc[i][j] = 0.0f;

    for (int kc = 0; kc < 64; kc += 32) {
        for (int e = t; e < 32 * 128; e += 256) {
            int k = e >> 7, o = e & 127;
            Bs[k][o] = g_w0t[(kc + k) * 128 + o];
        }
        for (int e = t; e < 128 * 32; e += 256) {
            int r = e >> 5, k = e & 31;
            int kk = kc + k;
            int n = s_n[r];
            float v;
            if (kk < 3) {
                v = __fsub_rn(xyz[((size_t)b * NTOT + 1 + n) * 3 + kk], s_nx[r >> 4][kk]);
            } else {
                v = points[((size_t)b * NTOT + 1 + n) * DPT + (kk - 3)];
            }
            As[k][r] = v;
        }
        __syncthreads();
#pragma unroll
        for (int k = 0; k < 32; k++) {
            float a[8], bb[8];
#pragma unroll
            for (int i = 0; i < 8; i++) a[i] = As[k][ty * 8 + i];
            const float4* bp = reinterpret_cast<const float4*>(&Bs[k][tx * 8]);
            float4 b0v = bp[0], b1v = bp[1];
            bb[0] = b0v.x; bb[1] = b0v.y; bb[2] = b0v.z; bb[3] = b0v.w;
            bb[4] = b1v.x; bb[5] = b1v.y; bb[6] = b1v.z; bb[7] = b1v.w;
#pragma unroll
            for (int i = 0; i < 8; i++)
#pragma unroll
                for (int j = 0; j < 8; j++) acc[i][j] += a[i] * bb[j];
        }
        __syncthreads();
    }

#pragma unroll
    for (int i = 0; i < 8; i++) {
        int r = ty * 8 + i;
        size_t row = (size_t)sbase * 16 + r;
#pragma unroll
        for (int j = 0; j < 8; j++) {
            int o = tx * 8 + j;
            float y = acc[i][j] * g_A0[o] + g_B0[o];
            g_y0[row * CH + o] = fmaxf(y, 0.0f);
        }
    }
}

// ---------------------------------------------------------------------------
// Layer 1: g_y0(128) @ W1t -> bn+relu -> maxpool over 16 neighbors -> out_pts
// ---------------------------------------------------------------------------
__global__ void __launch_bounds__(256) l1_kernel(float* __restrict__ out) {
    __shared__ __align__(16) float As[32][133];
    __shared__ __align__(16) float Bs[32][132];
    __shared__ float sRed[16][128];

    int ct = blockIdx.x;
    int sbase = ct * 8;
    int t = threadIdx.x;
    int tx = t & 15, ty = t >> 4;

    float acc[8][8];
#pragma unroll
    for (int i = 0; i < 8; i++)
#pragma unroll
        for (int j = 0; j < 8; j++) acc[i][j] = 0.0f;

    for (int kc = 0; kc < 128; kc += 32) {
        for (int e = t; e < 32 * 128; e += 256) {
            int k = e >> 7, o = e & 127;
            Bs[k][o] = g_w1t[(kc + k) * 128 + o];
        }
        for (int e = t; e < 128 * 32; e += 256) {
            int r = e >> 5, k = e & 31;
            As[k][r] = g_y0[((size_t)sbase * 16 + r) * CH + kc + k];
        }
        __syncthreads();
#pragma unroll
        for (int k = 0; k < 32; k++) {
            float a[8], bb[8];
#pragma unroll
            for (int i = 0; i < 8; i++) a[i] = As[k][ty * 8 + i];
            const float4* bp = reinterpret_cast<const float4*>(&Bs[k][tx * 8]);
            float4 b0v = bp[0], b1v = bp[1];
            bb[0] = b0v.x; bb[1] = b0v.y; bb[2] = b0v.z; bb[3] = b0v.w;
            bb[4] = b1v.x; bb[5] = b1v.y; bb[6] = b1v.z; bb[7] = b1v.w;
#pragma unroll
            for (int i = 0; i < 8; i++)
#pragma unroll
                for (int j = 0; j < 8; j++) acc[i][j] += a[i] * bb[j];
        }
        __syncthreads();
    }

    // bn+relu then per-thread max over its 8 rows (a half-sample: j 0..7 or 8..15)
    float m[8];
#pragma unroll
    for (int j = 0; j < 8; j++) {
        int o = tx * 8 + j;
        float A = g_A1[o], B = g_B1[o];
        float mm = -1e30f;
#pragma unroll
        for (int i = 0; i < 8; i++) {
            float y = acc[i][j] * A + B;
            y = fmaxf(y, 0.0f);
            mm = fmaxf(mm, y);
        }
        m[j] = mm;
    }
#pragma unroll
    for (int j = 0; j < 8; j++) sRed[ty][tx * 8 + j] = m[j];
    __syncthreads();

    for (int e = t; e < 8 * 128; e += 256) {
        int sl = e >> 7, o = e & 127;
        float v = fmaxf(sRed[2 * sl][o], sRed[2 * sl + 1][o]);
        int srow = sbase + sl;
        int bb2 = srow >> 10, ss = srow & 1023;
        out[OXYZ + ((size_t)bb2 * 1025 + 1 + ss) * CH + o] = v;
    }
}

// ---------------------------------------------------------------------------
// cls token branch: 2-layer MLP on one 64-dim vector per batch
// ---------------------------------------------------------------------------
__global__ void __launch_bounds__(128) cls_kernel(
    const float* __restrict__ xyz, const float* __restrict__ points,
    const float* __restrict__ w0, const float* __restrict__ b0,
    const float* __restrict__ g0, const float* __restrict__ bt0,
    const float* __restrict__ m0, const float* __restrict__ v0,
    const float* __restrict__ w1, const float* __restrict__ b1,
    const float* __restrict__ g1, const float* __restrict__ bt1,
    const float* __restrict__ m1, const float* __restrict__ v1,
    float* __restrict__ out) {
    int b = blockIdx.x, t = threadIdx.x;
    __shared__ float fin[64], h0[128];
    if (t < 3)            fin[t] = xyz[(size_t)b * NTOT * 3 + t];
    if (t >= 3 && t < 64) fin[t] = points[(size_t)b * NTOT * DPT + (t - 3)];
    __syncthreads();

    float acc = 0.0f;
    for (int c = 0; c < 64; c++) acc += fin[c] * w0[t * 64 + c];
    float y = (acc + b0[t] - m0[t]) * g0[t] / sqrtf(v0[t] + EPSV) + bt0[t];
    h0[t] = fmaxf(y, 0.0f);
    __syncthreads();

    acc = 0.0f;
    for (int c = 0; c < 128; c++) acc += h0[c] * w1[t * 128 + c];
    y = (acc + b1[t] - m1[t]) * g1[t] / sqrtf(v1[t] + EPSV) + bt1[t];
    out[OXYZ + (size_t)b * 1025 * CH + t] = fmaxf(y, 0.0f);
}

// ---------------------------------------------------------------------------
// launch
// ---------------------------------------------------------------------------
extern "C" void kernel_launch(void* const* d_in, const int* in_sizes, int n_in,
                              void* d_out, int out_size) {
    // dict insertion order:
    // 0 xyz, 1 points,
    // 2..7   sa_w0,  sa_b0,  sa_g0,  sa_bt0,  sa_m0,  sa_v0,
    // 8..13  cls_w0, cls_b0, cls_g0, cls_bt0, cls_m0, cls_v0,
    // 14..19 sa_w1,  sa_b1,  sa_g1,  sa_bt1,  sa_m1,  sa_v1,
    // 20..25 cls_w1, cls_b1, cls_g1, cls_bt1, cls_m1, cls_v1
    const float* xyz    = (const float*)d_in[0];
    const float* points = (const float*)d_in[1];
    const float* sa_w0  = (const float*)d_in[2];
    const float* sa_b0  = (const float*)d_in[3];
    const float* sa_g0  = (const float*)d_in[4];
    const float* sa_bt0 = (const float*)d_in[5];
    const float* sa_m0  = (const float*)d_in[6];
    const float* sa_v0  = (const float*)d_in[7];
    const float* cl_w0  = (const float*)d_in[8];
    const float* cl_b0  = (const float*)d_in[9];
    const float* cl_g0  = (const float*)d_in[10];
    const float* cl_bt0 = (const float*)d_in[11];
    const float* cl_m0  = (const float*)d_in[12];
    const float* cl_v0  = (const float*)d_in[13];
    const float* sa_w1  = (const float*)d_in[14];
    const float* sa_b1  = (const float*)d_in[15];
    const float* sa_g1  = (const float*)d_in[16];
    const float* sa_bt1 = (const float*)d_in[17];
    const float* sa_m1  = (const float*)d_in[18];
    const float* sa_v1  = (const float*)d_in[19];
    const float* cl_w1  = (const float*)d_in[20];
    const float* cl_b1  = (const float*)d_in[21];
    const float* cl_g1  = (const float*)d_in[22];
    const float* cl_bt1 = (const float*)d_in[23];
    const float* cl_m1  = (const float*)d_in[24];
    const float* cl_v1  = (const float*)d_in[25];
    float* out = (float*)d_out;

    prep_kernel<<<1, 256>>>(sa_w0, sa_b0, sa_g0, sa_bt0, sa_m0, sa_v0,
                            sa_w1, sa_b1, sa_g1, sa_bt1, sa_m1, sa_v1);
    pnorm_kernel<<<(BATCH * NR + 255) / 256, 256>>>(xyz);
    fps_kernel<<<BATCH, 1024>>>(xyz);
    newxyz_kernel<<<(BATCH * NP + 255) / 256, 256>>>(xyz, out);
    knn_kernel<<<BATCH * 8, 128>>>(xyz);
    l0_kernel<<<BATCH * NP / 8, 256>>>(xyz, points);
    l1_kernel<<<BATCH * NP / 8, 256>>>(out);
    cls_kernel<<<BATCH, 128>>>(xyz, points,
                               cl_w0, cl_b0, cl_g0, cl_bt0, cl_m0, cl_v0,
                               cl_w1, cl_b1, cl_g1, cl_bt1, cl_m1, cl_v1,
                               out);
}

// round 4
// speedup vs baseline: 1.4146x; 1.4146x over previous
#include <cuda_runtime.h>
#include <math.h>

#define BATCH   8
#define NTOT    4097
#define NR      4096
#define DPT     61
#define NP      1024
#define NS      16
#define CH      128
#define EPSV    1e-5f
#define OXYZ    (BATCH*1025*3)   // offset of out_pts in flattened output

// ----------------------------- device scratch ------------------------------
__device__ int   g_fid[BATCH * NP];
__device__ float g_newxyz[BATCH * NP * 3];
__device__ int   g_knn[BATCH * NP * NS];
__device__ float g_y0[(size_t)BATCH * NP * NS * CH];   // 64 MB
__device__ float g_w0t[64 * CH];                        // [cin][cout]
__device__ float g_w1t[CH * CH];                        // [cin][cout]
__device__ float g_A0[CH], g_B0[CH], g_A1[CH], g_B1[CH];

// packed f32x2 helpers (sm_103a): ptxas only emits FFMA2 from explicit PTX
#define PACKDUP(dst, s) do { unsigned _u = __float_as_uint(s); \
    asm("mov.b64 %0, {%1, %1};" : "=l"(dst) : "r"(_u)); } while (0)
#define FFMA2(acc, a, b) \
    asm("fma.rn.f32x2 %0, %1, %2, %0;" : "+l"(acc) : "l"(a), "l"(b))
#define UNPACK2(lo, hi, v) \
    asm("mov.b64 {%0, %1}, %2;" : "=f"(lo), "=f"(hi) : "l"(v))

// ---------------------------------------------------------------------------
// prep: transpose SA weights, fold BN:  bn(Wx+b) = (Wx)*A + B
// ---------------------------------------------------------------------------
__global__ void prep_kernel(const float* __restrict__ w0, const float* __restrict__ b0,
                            const float* __restrict__ g0, const float* __restrict__ bt0,
                            const float* __restrict__ m0, const float* __restrict__ v0,
                            const float* __restrict__ w1, const float* __restrict__ b1,
                            const float* __restrict__ g1, const float* __restrict__ bt1,
                            const float* __restrict__ m1, const float* __restrict__ v1) {
    int t = threadIdx.x;
    for (int i = t; i < 64 * CH; i += 256) {
        int c = i >> 7, o = i & 127;
        g_w0t[i] = w0[o * 64 + c];
    }
    for (int i = t; i < CH * CH; i += 256) {
        int c = i >> 7, o = i & 127;
        g_w1t[i] = w1[o * CH + c];
    }
    if (t < CH) {
        float a0 = g0[t] / sqrtf(v0[t] + EPSV);
        g_A0[t] = a0;
        g_B0[t] = (b0[t] - m0[t]) * a0 + bt0[t];
        float a1 = g1[t] / sqrtf(v1[t] + EPSV);
        g_A1[t] = a1;
        g_B1[t] = (b1[t] - m1[t]) * a1 + bt1[t];
    }
}

// ---------------------------------------------------------------------------
// FPS: one CTA/batch, 1024 threads * 4 pts in regs, xyz tile in dynamic smem.
// ONE barrier per iteration: per-warp redux -> double-buffered smem -> every
// warp redundantly reduces the 32 warp results. Exact reference arithmetic.
// ---------------------------------------------------------------------------
__global__ void __launch_bounds__(1024) fps_kernel(const float* __restrict__ xyz) {
    extern __shared__ float sh[];
    float* s_x = sh;            // [4096]
    float* s_y = sh + NR;       // [4096]
    float* s_z = sh + 2 * NR;   // [4096]
    __shared__ unsigned s_uv[2][32];
    __shared__ unsigned s_ui[2][32];

    int b = blockIdx.x;
    int tid = threadIdx.x;
    int lane = tid & 31, wid = tid >> 5;
    const float* base = xyz + ((size_t)b * NTOT + 1) * 3;

    for (int i = tid; i < NR * 3; i += 1024) {
        float v = base[i];
        int p = i / 3, c = i - 3 * p;
        if (c == 0) s_x[p] = v; else if (c == 1) s_y[p] = v; else s_z[p] = v;
    }
    __syncthreads();

    float px[4], py[4], pz[4], dd[4];
#pragma unroll
    for (int i = 0; i < 4; i++) {
        int p = tid * 4 + i;
        px[i] = s_x[p]; py[i] = s_y[p]; pz[i] = s_z[p];
        dd[i] = 1e10f;
    }

    int far = 0;
    for (int it = 0; it < NP; it++) {
        if (tid == 0) g_fid[b * NP + it] = far;
        float cx = s_x[far], cy = s_y[far], cz = s_z[far];

        float bv = -1.0f; int bi = 0;
#pragma unroll
        for (int i = 0; i < 4; i++) {
            float dx = __fsub_rn(px[i], cx);
            float dy = __fsub_rn(py[i], cy);
            float dz = __fsub_rn(pz[i], cz);
            float d = __fadd_rn(__fadd_rn(__fmul_rn(dx, dx), __fmul_rn(dy, dy)),
                                __fmul_rn(dz, dz));
            dd[i] = fminf(dd[i], d);
            if (dd[i] > bv) { bv = dd[i]; bi = tid * 4 + i; }
        }
        unsigned ub = __float_as_uint(bv);                     // dd >= 0: monotonic
        unsigned m  = __reduce_max_sync(0xffffffffu, ub);
        unsigned cd = (ub == m) ? (unsigned)bi : 0xffffffffu;  // first-index tiebreak
        unsigned wi = __reduce_min_sync(0xffffffffu, cd);

        int pb = it & 1;
        if (lane == 0) { s_uv[pb][wid] = m; s_ui[pb][wid] = wi; }
        __syncthreads();
        unsigned v  = s_uv[pb][lane];
        unsigned ii = s_ui[pb][lane];
        unsigned m2 = __reduce_max_sync(0xffffffffu, v);
        unsigned c2 = (v == m2) ? ii : 0xffffffffu;
        far = (int)__reduce_min_sync(0xffffffffu, c2);
    }
}

// ---------------------------------------------------------------------------
// new_xyz gather + out_xyz write (rows 0..1024 per batch)
// ---------------------------------------------------------------------------
__global__ void newxyz_kernel(const float* __restrict__ xyz, float* __restrict__ out) {
    int i = blockIdx.x * 256 + threadIdx.x;
    if (i < BATCH * NP) {
        int b = i >> 10, s = i & 1023;
        int f = g_fid[i];
        const float* q = xyz + ((size_t)b * NTOT + 1 + f) * 3;
        float x = q[0], y = q[1], z = q[2];
        g_newxyz[i * 3 + 0] = x;
        g_newxyz[i * 3 + 1] = y;
        g_newxyz[i * 3 + 2] = z;
        float* o = out + ((size_t)b * 1025 + 1 + s) * 3;
        o[0] = x; o[1] = y; o[2] = z;
        if (s == 0) {
            const float* c = xyz + (size_t)b * NTOT * 3;
            float* oc = out + (size_t)b * 1025 * 3;
            oc[0] = c[0]; oc[1] = c[1]; oc[2] = c[2];
        }
    }
}

// ---------------------------------------------------------------------------
// kNN-16: 128 queries/CTA, candidate tiles in smem (pnorm computed inline),
// per-thread 16-entry worst-evict list in smem. Exact reference arithmetic.
// ---------------------------------------------------------------------------
#define KTILE 512
__global__ void __launch_bounds__(128) knn_kernel(const float* __restrict__ xyz) {
    __shared__ float tx_[KTILE], ty_[KTILE], tz_[KTILE], tn_[KTILE];
    __shared__ float hv[16][128];
    __shared__ int   hi[16][128];

    int b  = blockIdx.x >> 3;
    int qt = blockIdx.x & 7;
    int t  = threadIdx.x;
    int s  = qt * 128 + t;
    int srow = b * NP + s;

    float qx = g_newxyz[srow * 3 + 0];
    float qy = g_newxyz[srow * 3 + 1];
    float qz = g_newxyz[srow * 3 + 2];
    float qn = __fadd_rn(__fadd_rn(__fmul_rn(qx, qx), __fmul_rn(qy, qy)), __fmul_rn(qz, qz));

    const float INF = __int_as_float(0x7f800000);
#pragma unroll
    for (int k = 0; k < 16; k++) { hv[k][t] = INF; hi[k][t] = 0x7fffffff; }
    float wv = INF; int ws = 0;

    const float* base = xyz + ((size_t)b * NTOT + 1) * 3;
    for (int tile = 0; tile < NR; tile += KTILE) {
        __syncthreads();
        for (int e = t; e < KTILE; e += 128) {
            int p = tile + e;
            float x = base[p * 3 + 0];
            float y = base[p * 3 + 1];
            float z = base[p * 3 + 2];
            tx_[e] = x; ty_[e] = y; tz_[e] = z;
            tn_[e] = __fadd_rn(__fadd_rn(__fmul_rn(x, x), __fmul_rn(y, y)), __fmul_rn(z, z));
        }
        __syncthreads();
        for (int j = 0; j < KTILE; j++) {
            float dot = __fadd_rn(__fadd_rn(__fmul_rn(qx, tx_[j]), __fmul_rn(qy, ty_[j])),
                                  __fmul_rn(qz, tz_[j]));
            float d2 = __fsub_rn(__fadd_rn(qn, tn_[j]), __fmul_rn(2.0f, dot));
            if (d2 < wv) {
                hv[ws][t] = d2; hi[ws][t] = tile + j;
                float nwv = hv[0][t]; int nws = 0; int nwi = hi[0][t];
#pragma unroll
                for (int k = 1; k < 16; k++) {
                    float v = hv[k][t]; int ii = hi[k][t];
                    if (v > nwv || (v == nwv && ii > nwi)) { nwv = v; nws = k; nwi = ii; }
                }
                wv = nwv; ws = nws;
            }
        }
    }
#pragma unroll
    for (int k = 0; k < 16; k++) g_knn[(size_t)srow * NS + k] = hi[k][t];
}

// ---------------------------------------------------------------------------
// Layer 0: gathered feat(64) @ W0t -> bn+relu -> g_y0. 128x128 tile, FFMA2.
// ---------------------------------------------------------------------------
__global__ void __launch_bounds__(256) l0_kernel(const float* __restrict__ xyz,
                                                 const float* __restrict__ points) {
    __shared__ __align__(16) float As[32][133];
    __shared__ __align__(16) float Bs[32][132];
    __shared__ int   s_n[128];
    __shared__ float s_nx[8][3];

    int ct = blockIdx.x;
    int sbase = ct * 8;
    int b = sbase >> 10;
    int t = threadIdx.x;
    int tx = t & 15, ty = t >> 4;

    if (t < 128) s_n[t] = g_knn[(size_t)(sbase + (t >> 4)) * NS + (t & 15)];
    if (t < 24)  s_nx[t / 3][t % 3] = g_newxyz[(sbase + t / 3) * 3 + (t % 3)];
    __syncthreads();

    unsigned long long acc2[8][4];
#pragma unroll
    for (int i = 0; i < 8; i++)
#pragma unroll
        for (int j = 0; j < 4; j++) acc2[i][j] = 0ull;

    for (int kc = 0; kc < 64; kc += 32) {
        for (int e = t; e < 32 * 128; e += 256) {
            int k = e >> 7, o = e & 127;
            Bs[k][o] = g_w0t[(kc + k) * 128 + o];
        }
        for (int e = t; e < 128 * 32; e += 256) {
            int r = e >> 5, k = e & 31;
            int kk = kc + k;
            int n = s_n[r];
            float v;
            if (kk < 3) {
                v = __fsub_rn(xyz[((size_t)b * NTOT + 1 + n) * 3 + kk], s_nx[r >> 4][kk]);
            } else {
                v = points[((size_t)b * NTOT + 1 + n) * DPT + (kk - 3)];
            }
            As[k][r] = v;
        }
        __syncthreads();
#pragma unroll
        for (int k = 0; k < 32; k++) {
            float a_[8];
#pragma unroll
            for (int i = 0; i < 8; i++) a_[i] = As[k][ty * 8 + i];
            const unsigned long long* bp =
                reinterpret_cast<const unsigned long long*>(&Bs[k][tx * 8]);
            unsigned long long b2[4];
#pragma unroll
            for (int j = 0; j < 4; j++) b2[j] = bp[j];
#pragma unroll
            for (int i = 0; i < 8; i++) {
                unsigned long long a2;
                PACKDUP(a2, a_[i]);
#pragma unroll
                for (int j = 0; j < 4; j++) FFMA2(acc2[i][j], a2, b2[j]);
            }
        }
        __syncthreads();
    }

#pragma unroll
    for (int i = 0; i < 8; i++) {
        int r = ty * 8 + i;
        size_t row = (size_t)sbase * 16 + r;
#pragma unroll
        for (int j = 0; j < 4; j++) {
            float lo, hiv;
            UNPACK2(lo, hiv, acc2[i][j]);
            int o = tx * 8 + 2 * j;
            float y0 = lo  * g_A0[o]     + g_B0[o];
            float y1 = hiv * g_A0[o + 1] + g_B0[o + 1];
            g_y0[row * CH + o]     = fmaxf(y0, 0.0f);
            g_y0[row * CH + o + 1] = fmaxf(y1, 0.0f);
        }
    }
}

// ---------------------------------------------------------------------------
// Layer 1: g_y0(128) @ W1t -> bn+relu -> maxpool(16) -> out_pts. FFMA2.
// ---------------------------------------------------------------------------
__global__ void __launch_bounds__(256) l1_kernel(float* __restrict__ out) {
    __shared__ __align__(16) float As[32][133];
    __shared__ __align__(16) float Bs[32][132];
    __shared__ float sRed[16][128];

    int ct = blockIdx.x;
    int sbase = ct * 8;
    int t = threadIdx.x;
    int tx = t & 15, ty = t >> 4;

    unsigned long long acc2[8][4];
#pragma unroll
    for (int i = 0; i < 8; i++)
#pragma unroll
        for (int j = 0; j < 4; j++) acc2[i][j] = 0ull;

    for (int kc = 0; kc < 128; kc += 32) {
        for (int e = t; e < 32 * 128; e += 256) {
            int k = e >> 7, o = e & 127;
            Bs[k][o] = g_w1t[(kc + k) * 128 + o];
        }
        for (int e = t; e < 128 * 32; e += 256) {
            int r = e >> 5, k = e & 31;
            As[k][r] = g_y0[((size_t)sbase * 16 + r) * CH + kc + k];
        }
        __syncthreads();
#pragma unroll
        for (int k = 0; k < 32; k++) {
            float a_[8];
#pragma unroll
            for (int i = 0; i < 8; i++) a_[i] = As[k][ty * 8 + i];
            const unsigned long long* bp =
                reinterpret_cast<const unsigned long long*>(&Bs[k][tx * 8]);
            unsigned long long b2[4];
#pragma unroll
            for (int j = 0; j < 4; j++) b2[j] = bp[j];
#pragma unroll
            for (int i = 0; i < 8; i++) {
                unsigned long long a2;
                PACKDUP(a2, a_[i]);
#pragma unroll
                for (int j = 0; j < 4; j++) FFMA2(acc2[i][j], a2, b2[j]);
            }
        }
        __syncthreads();
    }

    // bn+relu then per-thread max over its 8 rows
    float m[8];
#pragma unroll
    for (int j = 0; j < 4; j++) {
        int o = tx * 8 + 2 * j;
        float A0v = g_A1[o], B0v = g_B1[o];
        float A1v = g_A1[o + 1], B1v = g_B1[o + 1];
        float m0 = -1e30f, m1 = -1e30f;
#pragma unroll
        for (int i = 0; i < 8; i++) {
            float lo, hiv;
            UNPACK2(lo, hiv, acc2[i][j]);
            m0 = fmaxf(m0, fmaxf(lo  * A0v + B0v, 0.0f));
            m1 = fmaxf(m1, fmaxf(hiv * A1v + B1v, 0.0f));
        }
        m[2 * j] = m0; m[2 * j + 1] = m1;
    }
#pragma unroll
    for (int j = 0; j < 8; j++) sRed[ty][tx * 8 + j] = m[j];
    __syncthreads();

    for (int e = t; e < 8 * 128; e += 256) {
        int sl = e >> 7, o = e & 127;
        float v = fmaxf(sRed[2 * sl][o], sRed[2 * sl + 1][o]);
        int srow = sbase + sl;
        int bb2 = srow >> 10, ss = srow & 1023;
        out[OXYZ + ((size_t)bb2 * 1025 + 1 + ss) * CH + o] = v;
    }
}

// ---------------------------------------------------------------------------
// cls token branch
// ---------------------------------------------------------------------------
__global__ void __launch_bounds__(128) cls_kernel(
    const float* __restrict__ xyz, const float* __restrict__ points,
    const float* __restrict__ w0, const float* __restrict__ b0,
    const float* __restrict__ g0, const float* __restrict__ bt0,
    const float* __restrict__ m0, const float* __restrict__ v0,
    const float* __restrict__ w1, const float* __restrict__ b1,
    const float* __restrict__ g1, const float* __restrict__ bt1,
    const float* __restrict__ m1, const float* __restrict__ v1,
    float* __restrict__ out) {
    int b = blockIdx.x, t = threadIdx.x;
    __shared__ float fin[64], h0[128];
    if (t < 3)            fin[t] = xyz[(size_t)b * NTOT * 3 + t];
    if (t >= 3 && t < 64) fin[t] = points[(size_t)b * NTOT * DPT + (t - 3)];
    __syncthreads();

    float acc = 0.0f;
    for (int c = 0; c < 64; c++) acc += fin[c] * w0[t * 64 + c];
    float y = (acc + b0[t] - m0[t]) * g0[t] / sqrtf(v0[t] + EPSV) + bt0[t];
    h0[t] = fmaxf(y, 0.0f);
    __syncthreads();

    acc = 0.0f;
    for (int c = 0; c < 128; c++) acc += h0[c] * w1[t * 128 + c];
    y = (acc + b1[t] - m1[t]) * g1[t] / sqrtf(v1[t] + EPSV) + bt1[t];
    out[OXYZ + (size_t)b * 1025 * CH + t] = fmaxf(y, 0.0f);
}

// ---------------------------------------------------------------------------
// launch
// ---------------------------------------------------------------------------
extern "C" void kernel_launch(void* const* d_in, const int* in_sizes, int n_in,
                              void* d_out, int out_size) {
    const float* xyz    = (const float*)d_in[0];
    const float* points = (const float*)d_in[1];
    const float* sa_w0  = (const float*)d_in[2];
    const float* sa_b0  = (const float*)d_in[3];
    const float* sa_g0  = (const float*)d_in[4];
    const float* sa_bt0 = (const float*)d_in[5];
    const float* sa_m0  = (const float*)d_in[6];
    const float* sa_v0  = (const float*)d_in[7];
    const float* cl_w0  = (const float*)d_in[8];
    const float* cl_b0  = (const float*)d_in[9];
    const float* cl_g0  = (const float*)d_in[10];
    const float* cl_bt0 = (const float*)d_in[11];
    const float* cl_m0  = (const float*)d_in[12];
    const float* cl_v0  = (const float*)d_in[13];
    const float* sa_w1  = (const float*)d_in[14];
    const float* sa_b1  = (const float*)d_in[15];
    const float* sa_g1  = (const float*)d_in[16];
    const float* sa_bt1 = (const float*)d_in[17];
    const float* sa_m1  = (const float*)d_in[18];
    const float* sa_v1  = (const float*)d_in[19];
    const float* cl_w1  = (const float*)d_in[20];
    const float* cl_b1  = (const float*)d_in[21];
    const float* cl_g1  = (const float*)d_in[22];
    const float* cl_bt1 = (const float*)d_in[23];
    const float* cl_m1  = (const float*)d_in[24];
    const float* cl_v1  = (const float*)d_in[25];
    float* out = (float*)d_out;

    static bool attr_set = false;
    if (!attr_set) {
        cudaFuncSetAttribute(fps_kernel, cudaFuncAttributeMaxDynamicSharedMemorySize,
                             NR * 3 * sizeof(float));
        attr_set = true;
    }

    prep_kernel<<<1, 256>>>(sa_w0, sa_b0, sa_g0, sa_bt0, sa_m0, sa_v0,
                            sa_w1, sa_b1, sa_g1, sa_bt1, sa_m1, sa_v1);
    fps_kernel<<<BATCH, 1024, NR * 3 * sizeof(float)>>>(xyz);
    newxyz_kernel<<<(BATCH * NP + 255) / 256, 256>>>(xyz, out);
    knn_kernel<<<BATCH * 8, 128>>>(xyz);
    l0_kernel<<<BATCH * NP / 8, 256>>>(xyz, points);
    l1_kernel<<<BATCH * NP / 8, 256>>>(out);
    cls_kernel<<<BATCH, 128>>>(xyz, points,
                               cl_w0, cl_b0, cl_g0, cl_bt0, cl_m0, cl_v0,
                               cl_w1, cl_b1, cl_g1, cl_bt1, cl_m1, cl_v1,
                               out);
}

// round 5
// speedup vs baseline: 2.2071x; 1.5602x over previous
#include <cuda_runtime.h>
#include <math.h>

#define BATCH   8
#define NTOT    4097
#define NR      4096
#define DPT     61
#define NP      1024
#define NS      16
#define CH      128
#define EPSV    1e-5f
#define OXYZ    (BATCH*1025*3)   // offset of out_pts in flattened output

typedef unsigned long long ull;

// ----------------------------- device scratch ------------------------------
__device__ int   g_fid[BATCH * NP];
__device__ float g_newxyz[BATCH * NP * 3];
__device__ int   g_knn[BATCH * NP * NS];
__device__ float g_y0[(size_t)BATCH * NP * NS * CH];   // 64 MB
__device__ float g_w0t[64 * CH];                        // [cin][cout]
__device__ float g_w1t[CH * CH];                        // [cin][cout]
__device__ float g_A0[CH], g_B0[CH], g_A1[CH], g_B1[CH];

// packed f32x2 helpers (sm_103a): ptxas only emits packed math from explicit PTX
#define PACKDUP(dst, s) do { unsigned _u = __float_as_uint(s); \
    asm("mov.b64 %0, {%1, %1};" : "=l"(dst) : "r"(_u)); } while (0)
#define PACK2(dst, lo, hi) \
    asm("mov.b64 %0, {%1, %2};" : "=l"(dst) : "f"(lo), "f"(hi))
#define FFMA2(acc, a, b) \
    asm("fma.rn.f32x2 %0, %1, %2, %0;" : "+l"(acc) : "l"(a), "l"(b))
#define ADD2(dst, a, b) \
    asm("add.rn.f32x2 %0, %1, %2;" : "=l"(dst) : "l"(a), "l"(b))
#define MUL2(dst, a, b) \
    asm("mul.rn.f32x2 %0, %1, %2;" : "=l"(dst) : "l"(a), "l"(b))
#define UNPACK2(lo, hi, v) \
    asm("mov.b64 {%0, %1}, %2;" : "=f"(lo), "=f"(hi) : "l"(v))

// ---------------------------------------------------------------------------
// prep: transpose SA weights, fold BN:  bn(Wx+b) = (Wx)*A + B
// ---------------------------------------------------------------------------
__global__ void prep_kernel(const float* __restrict__ w0, const float* __restrict__ b0,
                            const float* __restrict__ g0, const float* __restrict__ bt0,
                            const float* __restrict__ m0, const float* __restrict__ v0,
                            const float* __restrict__ w1, const float* __restrict__ b1,
                            const float* __restrict__ g1, const float* __restrict__ bt1,
                            const float* __restrict__ m1, const float* __restrict__ v1) {
    int t = threadIdx.x;
    for (int i = t; i < 64 * CH; i += 256) {
        int c = i >> 7, o = i & 127;
        g_w0t[i] = w0[o * 64 + c];
    }
    for (int i = t; i < CH * CH; i += 256) {
        int c = i >> 7, o = i & 127;
        g_w1t[i] = w1[o * CH + c];
    }
    if (t < CH) {
        float a0 = g0[t] / sqrtf(v0[t] + EPSV);
        g_A0[t] = a0;
        g_B0[t] = (b0[t] - m0[t]) * a0 + bt0[t];
        float a1 = g1[t] / sqrtf(v1[t] + EPSV);
        g_A1[t] = a1;
        g_B1[t] = (b1[t] - m1[t]) * a1 + bt1[t];
    }
}

// ---------------------------------------------------------------------------
// FPS: one CTA/batch, 1024 threads * 4 pts, packed f32x2 distance updates.
// a-b computed as a+(-b) (exact); mul/add .rn.f32x2 lanewise == scalar rn.
// One barrier per iteration (double-buffered warp results).
// ---------------------------------------------------------------------------
__global__ void __launch_bounds__(1024) fps_kernel(const float* __restrict__ xyz) {
    extern __shared__ float sh[];
    float* s_x = sh;            // [4096]
    float* s_y = sh + NR;       // [4096]
    float* s_z = sh + 2 * NR;   // [4096]
    __shared__ unsigned s_uv[2][32];
    __shared__ unsigned s_ui[2][32];

    int b = blockIdx.x;
    int tid = threadIdx.x;
    int lane = tid & 31, wid = tid >> 5;
    const float* base = xyz + ((size_t)b * NTOT + 1) * 3;

    for (int i = tid; i < NR * 3; i += 1024) {
        float v = base[i];
        int p = i / 3, c = i - 3 * p;
        if (c == 0) s_x[p] = v; else if (c == 1) s_y[p] = v; else s_z[p] = v;
    }
    __syncthreads();

    ull px2[2], py2[2], pz2[2];
    float dd[4];
#pragma unroll
    for (int j = 0; j < 2; j++) {
        int p = tid * 4 + 2 * j;
        PACK2(px2[j], s_x[p], s_x[p + 1]);
        PACK2(py2[j], s_y[p], s_y[p + 1]);
        PACK2(pz2[j], s_z[p], s_z[p + 1]);
        dd[2 * j] = 1e10f; dd[2 * j + 1] = 1e10f;
    }

    int far = 0;
    for (int it = 0; it < NP; it++) {
        if (tid == 0) g_fid[b * NP + it] = far;
        float cx = s_x[far], cy = s_y[far], cz = s_z[far];
        ull ncx2, ncy2, ncz2;
        PACKDUP(ncx2, -cx); PACKDUP(ncy2, -cy); PACKDUP(ncz2, -cz);

        float bv = -1.0f; int bi = 0;
#pragma unroll
        for (int j = 0; j < 2; j++) {
            ull dx2, dy2, dz2, m1, m2, m3, s1, d2p;
            ADD2(dx2, px2[j], ncx2);
            ADD2(dy2, py2[j], ncy2);
            ADD2(dz2, pz2[j], ncz2);
            MUL2(m1, dx2, dx2);
            MUL2(m2, dy2, dy2);
            MUL2(m3, dz2, dz2);
            ADD2(s1, m1, m2);
            ADD2(d2p, s1, m3);
            float d0, d1;
            UNPACK2(d0, d1, d2p);
            dd[2 * j]     = fminf(dd[2 * j], d0);
            dd[2 * j + 1] = fminf(dd[2 * j + 1], d1);
            if (dd[2 * j]     > bv) { bv = dd[2 * j];     bi = tid * 4 + 2 * j; }
            if (dd[2 * j + 1] > bv) { bv = dd[2 * j + 1]; bi = tid * 4 + 2 * j + 1; }
        }
        unsigned ub = __float_as_uint(bv);                     // dd >= 0: bit-monotonic
        unsigned m  = __reduce_max_sync(0xffffffffu, ub);
        unsigned cd = (ub == m) ? (unsigned)bi : 0xffffffffu;  // first-index tiebreak
        unsigned wi = __reduce_min_sync(0xffffffffu, cd);

        int pb = it & 1;
        if (lane == 0) { s_uv[pb][wid] = m; s_ui[pb][wid] = wi; }
        __syncthreads();
        unsigned v  = s_uv[pb][lane];
        unsigned ii = s_ui[pb][lane];
        unsigned m2r = __reduce_max_sync(0xffffffffu, v);
        unsigned c2 = (v == m2r) ? ii : 0xffffffffu;
        far = (int)__reduce_min_sync(0xffffffffu, c2);
    }
}

// ---------------------------------------------------------------------------
// new_xyz gather + out_xyz write
// ---------------------------------------------------------------------------
__global__ void newxyz_kernel(const float* __restrict__ xyz, float* __restrict__ out) {
    int i = blockIdx.x * 256 + threadIdx.x;
    if (i < BATCH * NP) {
        int b = i >> 10, s = i & 1023;
        int f = g_fid[i];
        const float* q = xyz + ((size_t)b * NTOT + 1 + f) * 3;
        float x = q[0], y = q[1], z = q[2];
        g_newxyz[i * 3 + 0] = x;
        g_newxyz[i * 3 + 1] = y;
        g_newxyz[i * 3 + 2] = z;
        float* o = out + ((size_t)b * 1025 + 1 + s) * 3;
        o[0] = x; o[1] = y; o[2] = z;
        if (s == 0) {
            const float* c = xyz + (size_t)b * NTOT * 3;
            float* oc = out + (size_t)b * 1025 * 3;
            oc[0] = c[0]; oc[1] = c[1]; oc[2] = c[2];
        }
    }
}

// ---------------------------------------------------------------------------
// kNN-16 v2: 4 threads per query, each scans 1024 candidates (stride-4 within
// float4 tiles) keeping a 16-entry register heap of packed u64 keys
// (ord(d2)<<32 | idx). Merge 4x16 -> 16 smallest by (d2, idx) == stable top_k.
// ---------------------------------------------------------------------------
#define QPB   64                   // queries per block
#define KTILE 1024                 // candidates per tile
__global__ void __launch_bounds__(256) knn_kernel(const float* __restrict__ xyz) {
    extern __shared__ unsigned char kshm[];
    float4* s_t  = (float4*)kshm;                    // [1024]  16 KB
    ull*    s_mr = (ull*)(kshm + KTILE * 16);        // [QPB][65] 33 KB

    int t = threadIdx.x;
    int q = t >> 2;            // query within block
    int sub = t & 3;           // candidate subset
    int srow = blockIdx.x * QPB + q;   // global sample row (b*1024+s)
    int b = srow >> 10;

    float qx = g_newxyz[srow * 3 + 0];
    float qy = g_newxyz[srow * 3 + 1];
    float qz = g_newxyz[srow * 3 + 2];
    float qn = __fadd_rn(__fadd_rn(__fmul_rn(qx, qx), __fmul_rn(qy, qy)), __fmul_rn(qz, qz));

    // heap: 16 packed keys; unique +inf sentinels (evicted largest-first)
    ull h[16];
#pragma unroll
    for (int k = 0; k < 16; k++)
        h[k] = (0xFF800000ull << 32) | (0xFFFFFFF0u + (unsigned)k);
    ull wkey = h[15];
    float wv = __int_as_float(0x7f800000);           // +inf

    const float* base = xyz + ((size_t)b * NTOT + 1) * 3;
    for (int tile = 0; tile < NR; tile += KTILE) {
        __syncthreads();
        for (int e = t; e < KTILE; e += 256) {
            int p = tile + e;
            float x = base[p * 3 + 0];
            float y = base[p * 3 + 1];
            float z = base[p * 3 + 2];
            float n = __fadd_rn(__fadd_rn(__fmul_rn(x, x), __fmul_rn(y, y)), __fmul_rn(z, z));
            s_t[e] = make_float4(x, y, z, n);
        }
        __syncthreads();
#pragma unroll 4
        for (int jj = 0; jj < KTILE / 4; jj++) {
            int j = jj * 4 + sub;
            float4 c = s_t[j];
            float dot = __fadd_rn(__fadd_rn(__fmul_rn(qx, c.x), __fmul_rn(qy, c.y)),
                                  __fmul_rn(qz, c.z));
            float d2 = __fsub_rn(__fadd_rn(qn, c.w), __fmul_rn(2.0f, dot));
            if (d2 < wv) {            // strict <: ascending idx => exact tie handling
                unsigned ub = __float_as_uint(d2);
                ub = ((int)ub < 0) ? ~ub : (ub | 0x80000000u);
                ull key = ((ull)ub << 32) | (unsigned)(tile + j);
#pragma unroll
                for (int k = 0; k < 16; k++) h[k] = (h[k] == wkey) ? key : h[k];
                wkey = h[0];
#pragma unroll
                for (int k = 1; k < 16; k++) wkey = (h[k] > wkey) ? h[k] : wkey;
                unsigned hi = (unsigned)(wkey >> 32);
                wv = __uint_as_float((hi & 0x80000000u) ? (hi & 0x7fffffffu) : ~hi);
            }
        }
    }

    // dump per-thread heaps, merge 64 -> 16 per query
#pragma unroll
    for (int k = 0; k < 16; k++) s_mr[q * 65 + sub * 16 + k] = h[k];
    __syncthreads();
    if (sub == 0) {
        ull* row = s_mr + q * 65;
        int* dst = g_knn + (size_t)srow * NS;
        for (int k = 0; k < 16; k++) {
            ull best = ~0ull; int bj = 0;
            for (int j = 0; j < 64; j++) {
                ull v = row[j];
                if (v < best) { best = v; bj = j; }
            }
            dst[k] = (int)(best & 0xffffffffu);
            row[bj] = ~0ull;
        }
    }
}

// ---------------------------------------------------------------------------
// Layer 0: gathered feat(64) @ W0t -> bn+relu -> g_y0. 128x128 tile, FFMA2.
// ---------------------------------------------------------------------------
__global__ void __launch_bounds__(256) l0_kernel(const float* __restrict__ xyz,
                                                 const float* __restrict__ points) {
    __shared__ __align__(16) float As[32][133];
    __shared__ __align__(16) float Bs[32][132];
    __shared__ int   s_n[128];
    __shared__ float s_nx[8][3];

    int ct = blockIdx.x;
    int sbase = ct * 8;
    int b = sbase >> 10;
    int t = threadIdx.x;
    int tx = t & 15, ty = t >> 4;

    if (t < 128) s_n[t] = g_knn[(size_t)(sbase + (t >> 4)) * NS + (t & 15)];
    if (t < 24)  s_nx[t / 3][t % 3] = g_newxyz[(sbase + t / 3) * 3 + (t % 3)];
    __syncthreads();

    ull acc2[8][4];
#pragma unroll
    for (int i = 0; i < 8; i++)
#pragma unroll
        for (int j = 0; j < 4; j++) acc2[i][j] = 0ull;

    for (int kc = 0; kc < 64; kc += 32) {
        for (int e = t; e < 32 * 128; e += 256) {
            int k = e >> 7, o = e & 127;
            Bs[k][o] = g_w0t[(kc + k) * 128 + o];
        }
        for (int e = t; e < 128 * 32; e += 256) {
            int r = e >> 5, k = e & 31;
            int kk = kc + k;
            int n = s_n[r];
            float v;
            if (kk < 3) {
                v = __fsub_rn(xyz[((size_t)b * NTOT + 1 + n) * 3 + kk], s_nx[r >> 4][kk]);
            } else {
                v = points[((size_t)b * NTOT + 1 + n) * DPT + (kk - 3)];
            }
            As[k][r] = v;
        }
        __syncthreads();
#pragma unroll
        for (int k = 0; k < 32; k++) {
            float a_[8];
#pragma unroll
            for (int i = 0; i < 8; i++) a_[i] = As[k][ty * 8 + i];
            const ull* bp = reinterpret_cast<const ull*>(&Bs[k][tx * 8]);
            ull b2[4];
#pragma unroll
            for (int j = 0; j < 4; j++) b2[j] = bp[j];
#pragma unroll
            for (int i = 0; i < 8; i++) {
                ull a2;
                PACKDUP(a2, a_[i]);
#pragma unroll
                for (int j = 0; j < 4; j++) FFMA2(acc2[i][j], a2, b2[j]);
            }
        }
        __syncthreads();
    }

#pragma unroll
    for (int i = 0; i < 8; i++) {
        int r = ty * 8 + i;
        size_t row = (size_t)sbase * 16 + r;
#pragma unroll
        for (int j = 0; j < 4; j++) {
            float lo, hiv;
            UNPACK2(lo, hiv, acc2[i][j]);
            int o = tx * 8 + 2 * j;
            float y0 = lo  * g_A0[o]     + g_B0[o];
            float y1 = hiv * g_A0[o + 1] + g_B0[o + 1];
            g_y0[row * CH + o]     = fmaxf(y0, 0.0f);
            g_y0[row * CH + o + 1] = fmaxf(y1, 0.0f);
        }
    }
}

// ---------------------------------------------------------------------------
// Layer 1: g_y0(128) @ W1t -> bn+relu -> maxpool(16) -> out_pts. FFMA2.
// ---------------------------------------------------------------------------
__global__ void __launch_bounds__(256) l1_kernel(float* __restrict__ out) {
    __shared__ __align__(16) float As[32][133];
    __shared__ __align__(16) float Bs[32][132];
    __shared__ float sRed[16][128];

    int ct = blockIdx.x;
    int sbase = ct * 8;
    int t = threadIdx.x;
    int tx = t & 15, ty = t >> 4;

    ull acc2[8][4];
#pragma unroll
    for (int i = 0; i < 8; i++)
#pragma unroll
        for (int j = 0; j < 4; j++) acc2[i][j] = 0ull;

    for (int kc = 0; kc < 128; kc += 32) {
        for (int e = t; e < 32 * 128; e += 256) {
            int k = e >> 7, o = e & 127;
            Bs[k][o] = g_w1t[(kc + k) * 128 + o];
        }
        for (int e = t; e < 128 * 32; e += 256) {
            int r = e >> 5, k = e & 31;
            As[k][r] = g_y0[((size_t)sbase * 16 + r) * CH + kc + k];
        }
        __syncthreads();
#pragma unroll
        for (int k = 0; k < 32; k++) {
            float a_[8];
#pragma unroll
            for (int i = 0; i < 8; i++) a_[i] = As[k][ty * 8 + i];
            const ull* bp = reinterpret_cast<const ull*>(&Bs[k][tx * 8]);
            ull b2[4];
#pragma unroll
            for (int j = 0; j < 4; j++) b2[j] = bp[j];
#pragma unroll
            for (int i = 0; i < 8; i++) {
                ull a2;
                PACKDUP(a2, a_[i]);
#pragma unroll
                for (int j = 0; j < 4; j++) FFMA2(acc2[i][j], a2, b2[j]);
            }
        }
        __syncthreads();
    }

    float m[8];
#pragma unroll
    for (int j = 0; j < 4; j++) {
        int o = tx * 8 + 2 * j;
        float A0v = g_A1[o], B0v = g_B1[o];
        float A1v = g_A1[o + 1], B1v = g_B1[o + 1];
        float m0 = -1e30f, m1 = -1e30f;
#pragma unroll
        for (int i = 0; i < 8; i++) {
            float lo, hiv;
            UNPACK2(lo, hiv, acc2[i][j]);
            m0 = fmaxf(m0, fmaxf(lo  * A0v + B0v, 0.0f));
            m1 = fmaxf(m1, fmaxf(hiv * A1v + B1v, 0.0f));
        }
        m[2 * j] = m0; m[2 * j + 1] = m1;
    }
#pragma unroll
    for (int j = 0; j < 8; j++) sRed[ty][tx * 8 + j] = m[j];
    __syncthreads();

    for (int e = t; e < 8 * 128; e += 256) {
        int sl = e >> 7, o = e & 127;
        float v = fmaxf(sRed[2 * sl][o], sRed[2 * sl + 1][o]);
        int srow = sbase + sl;
        int bb2 = srow >> 10, ss = srow & 1023;
        out[OXYZ + ((size_t)bb2 * 1025 + 1 + ss) * CH + o] = v;
    }
}

// ---------------------------------------------------------------------------
// cls token branch
// ---------------------------------------------------------------------------
__global__ void __launch_bounds__(128) cls_kernel(
    const float* __restrict__ xyz, const float* __restrict__ points,
    const float* __restrict__ w0, const float* __restrict__ b0,
    const float* __restrict__ g0, const float* __restrict__ bt0,
    const float* __restrict__ m0, const float* __restrict__ v0,
    const float* __restrict__ w1, const float* __restrict__ b1,
    const float* __restrict__ g1, const float* __restrict__ bt1,
    const float* __restrict__ m1, const float* __restrict__ v1,
    float* __restrict__ out) {
    int b = blockIdx.x, t = threadIdx.x;
    __shared__ float fin[64], h0[128];
    if (t < 3)            fin[t] = xyz[(size_t)b * NTOT * 3 + t];
    if (t >= 3 && t < 64) fin[t] = points[(size_t)b * NTOT * DPT + (t - 3)];
    __syncthreads();

    float acc = 0.0f;
    for (int c = 0; c < 64; c++) acc += fin[c] * w0[t * 64 + c];
    float y = (acc + b0[t] - m0[t]) * g0[t] / sqrtf(v0[t] + EPSV) + bt0[t];
    h0[t] = fmaxf(y, 0.0f);
    __syncthreads();

    acc = 0.0f;
    for (int c = 0; c < 128; c++) acc += h0[c] * w1[t * 128 + c];
    y = (acc + b1[t] - m1[t]) * g1[t] / sqrtf(v1[t] + EPSV) + bt1[t];
    out[OXYZ + (size_t)b * 1025 * CH + t] = fmaxf(y, 0.0f);
}

// ---------------------------------------------------------------------------
// launch
// ---------------------------------------------------------------------------
#define KNN_SHM (KTILE * 16 + QPB * 65 * 8)

extern "C" void kernel_launch(void* const* d_in, const int* in_sizes, int n_in,
                              void* d_out, int out_size) {
    const float* xyz    = (const float*)d_in[0];
    const float* points = (const float*)d_in[1];
    const float* sa_w0  = (const float*)d_in[2];
    const float* sa_b0  = (const float*)d_in[3];
    const float* sa_g0  = (const float*)d_in[4];
    const float* sa_bt0 = (const float*)d_in[5];
    const float* sa_m0  = (const float*)d_in[6];
    const float* sa_v0  = (const float*)d_in[7];
    const float* cl_w0  = (const float*)d_in[8];
    const float* cl_b0  = (const float*)d_in[9];
    const float* cl_g0  = (const float*)d_in[10];
    const float* cl_bt0 = (const float*)d_in[11];
    const float* cl_m0  = (const float*)d_in[12];
    const float* cl_v0  = (const float*)d_in[13];
    const float* sa_w1  = (const float*)d_in[14];
    const float* sa_b1  = (const float*)d_in[15];
    const float* sa_g1  = (const float*)d_in[16];
    const float* sa_bt1 = (const float*)d_in[17];
    const float* sa_m1  = (const float*)d_in[18];
    const float* sa_v1  = (const float*)d_in[19];
    const float* cl_w1  = (const float*)d_in[20];
    const float* cl_b1  = (const float*)d_in[21];
    const float* cl_g1  = (const float*)d_in[22];
    const float* cl_bt1 = (const float*)d_in[23];
    const float* cl_m1  = (const float*)d_in[24];
    const float* cl_v1  = (const float*)d_in[25];
    float* out = (float*)d_out;

    static bool attr_set = false;
    if (!attr_set) {
        cudaFuncSetAttribute(fps_kernel, cudaFuncAttributeMaxDynamicSharedMemorySize,
                             NR * 3 * sizeof(float));
        cudaFuncSetAttribute(knn_kernel, cudaFuncAttributeMaxDynamicSharedMemorySize,
                             KNN_SHM);
        attr_set = true;
    }

    prep_kernel<<<1, 256>>>(sa_w0, sa_b0, sa_g0, sa_bt0, sa_m0, sa_v0,
                            sa_w1, sa_b1, sa_g1, sa_bt1, sa_m1, sa_v1);
    fps_kernel<<<BATCH, 1024, NR * 3 * sizeof(float)>>>(xyz);
    newxyz_kernel<<<(BATCH * NP + 255) / 256, 256>>>(xyz, out);
    knn_kernel<<<BATCH * NP / QPB, 256, KNN_SHM>>>(xyz);
    l0_kernel<<<BATCH * NP / 8, 256>>>(xyz, points);
    l1_kernel<<<BATCH * NP / 8, 256>>>(out);
    cls_kernel<<<BATCH, 128>>>(xyz, points,
                               cl_w0, cl_b0, cl_g0, cl_bt0, cl_m0, cl_v0,
                               cl_w1, cl_b1, cl_g1, cl_bt1, cl_m1, cl_v1,
                               out);
}

// round 6
// speedup vs baseline: 2.2072x; 1.0000x over previous
#include <cuda_runtime.h>
#include <math.h>

#define BATCH   8
#define NTOT    4097
#define NR      4096
#define DPT     61
#define NP      1024
#define NS      16
#define CH      128
#define EPSV    1e-5f
#define OXYZ    (BATCH*1025*3)   // offset of out_pts in flattened output

typedef unsigned long long ull;

// ----------------------------- device scratch ------------------------------
__device__ int   g_fid[BATCH * NP];
__device__ float g_newxyz[BATCH * NP * 3];
__device__ int   g_knn[BATCH * NP * NS];
__device__ float g_y0[(size_t)BATCH * NP * NS * CH];   // 64 MB
__device__ float g_w0t[64 * CH];                        // [cin][cout]
__device__ float g_w1t[CH * CH];                        // [cin][cout]
__device__ float g_A0[CH], g_B0[CH], g_A1[CH], g_B1[CH];

// packed f32x2 helpers (sm_103a): ptxas only emits packed math from explicit PTX
#define PACKDUP(dst, s) do { unsigned _u = __float_as_uint(s); \
    asm("mov.b64 %0, {%1, %1};" : "=l"(dst) : "r"(_u)); } while (0)
#define PACK2(dst, lo, hi) \
    asm("mov.b64 %0, {%1, %2};" : "=l"(dst) : "f"(lo), "f"(hi))
#define FFMA2(acc, a, b) \
    asm("fma.rn.f32x2 %0, %1, %2, %0;" : "+l"(acc) : "l"(a), "l"(b))
#define FFMA2N(dst, a, b, c) \
    asm("fma.rn.f32x2 %0, %1, %2, %3;" : "=l"(dst) : "l"(a), "l"(b), "l"(c))
#define ADD2(dst, a, b) \
    asm("add.rn.f32x2 %0, %1, %2;" : "=l"(dst) : "l"(a), "l"(b))
#define MUL2(dst, a, b) \
    asm("mul.rn.f32x2 %0, %1, %2;" : "=l"(dst) : "l"(a), "l"(b))
#define UNPACK2(lo, hi, v) \
    asm("mov.b64 {%0, %1}, %2;" : "=f"(lo), "=f"(hi) : "l"(v))

// ---------------------------------------------------------------------------
// prep: transpose SA weights, fold BN:  bn(Wx+b) = (Wx)*A + B
// ---------------------------------------------------------------------------
__global__ void prep_kernel(const float* __restrict__ w0, const float* __restrict__ b0,
                            const float* __restrict__ g0, const float* __restrict__ bt0,
                            const float* __restrict__ m0, const float* __restrict__ v0,
                            const float* __restrict__ w1, const float* __restrict__ b1,
                            const float* __restrict__ g1, const float* __restrict__ bt1,
                            const float* __restrict__ m1, const float* __restrict__ v1) {
    int t = threadIdx.x;
    for (int i = t; i < 64 * CH; i += 256) {
        int c = i >> 7, o = i & 127;
        g_w0t[i] = w0[o * 64 + c];
    }
    for (int i = t; i < CH * CH; i += 256) {
        int c = i >> 7, o = i & 127;
        g_w1t[i] = w1[o * CH + c];
    }
    if (t < CH) {
        float a0 = g0[t] / sqrtf(v0[t] + EPSV);
        g_A0[t] = a0;
        g_B0[t] = (b0[t] - m0[t]) * a0 + bt0[t];
        float a1 = g1[t] / sqrtf(v1[t] + EPSV);
        g_A1[t] = a1;
        g_B1[t] = (b1[t] - m1[t]) * a1 + bt1[t];
    }
}

// ---------------------------------------------------------------------------
// FPS: one CTA/batch, 256 threads * 16 pts (8 packed pairs). Exact reference
// arithmetic (a-b as a+(-b); lanewise .rn packed == scalar rn). One barrier
// per iteration, 8-warp level-2 reduce done redundantly by every warp.
// ---------------------------------------------------------------------------
__global__ void __launch_bounds__(256) fps_kernel(const float* __restrict__ xyz) {
    extern __shared__ float sh[];
    float* s_x = sh;            // [4096]
    float* s_y = sh + NR;       // [4096]
    float* s_z = sh + 2 * NR;   // [4096]
    __shared__ unsigned s_uv[2][8];
    __shared__ unsigned s_ui[2][8];

    int b = blockIdx.x;
    int tid = threadIdx.x;
    int lane = tid & 31;
    int wid = tid >> 5;
    const float* base = xyz + ((size_t)b * NTOT + 1) * 3;

    for (int i = tid; i < NR * 3; i += 256) {
        float v = base[i];
        int p = i / 3, c = i - 3 * p;
        if (c == 0) s_x[p] = v; else if (c == 1) s_y[p] = v; else s_z[p] = v;
    }
    __syncthreads();

    int p0 = tid * 16;
    ull px2[8], py2[8], pz2[8];
    float dd[16];
#pragma unroll
    for (int j = 0; j < 8; j++) {
        int p = p0 + 2 * j;
        PACK2(px2[j], s_x[p], s_x[p + 1]);
        PACK2(py2[j], s_y[p], s_y[p + 1]);
        PACK2(pz2[j], s_z[p], s_z[p + 1]);
        dd[2 * j] = 1e10f; dd[2 * j + 1] = 1e10f;
    }

    int far = 0;
    for (int it = 0; it < NP; it++) {
        if (tid == 0) g_fid[b * NP + it] = far;
        float cx = s_x[far], cy = s_y[far], cz = s_z[far];
        ull ncx2, ncy2, ncz2;
        PACKDUP(ncx2, -cx); PACKDUP(ncy2, -cy); PACKDUP(ncz2, -cz);

        float tm = -1.0f;
#pragma unroll
        for (int j = 0; j < 8; j++) {
            ull dx2, dy2, dz2, m1, m2, m3, s1, d2p;
            ADD2(dx2, px2[j], ncx2);
            ADD2(dy2, py2[j], ncy2);
            ADD2(dz2, pz2[j], ncz2);
            MUL2(m1, dx2, dx2);
            MUL2(m2, dy2, dy2);
            MUL2(m3, dz2, dz2);
            ADD2(s1, m1, m2);
            ADD2(d2p, s1, m3);
            float d0, d1;
            UNPACK2(d0, d1, d2p);
            dd[2 * j]     = fminf(dd[2 * j], d0);
            dd[2 * j + 1] = fminf(dd[2 * j + 1], d1);
            tm = fmaxf(tm, fmaxf(dd[2 * j], dd[2 * j + 1]));
        }
        // first local index achieving tm (descending chain keeps lowest i)
        int bi = p0 + 15;
#pragma unroll
        for (int i = 14; i >= 0; i--) bi = (dd[i] == tm) ? (p0 + i) : bi;

        unsigned ub = __float_as_uint(tm);                     // dd >= 0: bit-monotonic
        unsigned m  = __reduce_max_sync(0xffffffffu, ub);
        unsigned cd = (ub == m) ? (unsigned)bi : 0xffffffffu;  // first-index tiebreak
        unsigned wi = __reduce_min_sync(0xffffffffu, cd);

        int pb = it & 1;
        if (lane == 0) { s_uv[pb][wid] = m; s_ui[pb][wid] = wi; }
        __syncthreads();
        unsigned v   = s_uv[pb][lane & 7];
        unsigned ii  = s_ui[pb][lane & 7];
        unsigned m2r = __reduce_max_sync(0xffffffffu, v);
        unsigned c2  = (v == m2r) ? ii : 0xffffffffu;
        far = (int)__reduce_min_sync(0xffffffffu, c2);
    }
}

// ---------------------------------------------------------------------------
// new_xyz gather + out_xyz write
// ---------------------------------------------------------------------------
__global__ void newxyz_kernel(const float* __restrict__ xyz, float* __restrict__ out) {
    int i = blockIdx.x * 256 + threadIdx.x;
    if (i < BATCH * NP) {
        int b = i >> 10, s = i & 1023;
        int f = g_fid[i];
        const float* q = xyz + ((size_t)b * NTOT + 1 + f) * 3;
        float x = q[0], y = q[1], z = q[2];
        g_newxyz[i * 3 + 0] = x;
        g_newxyz[i * 3 + 1] = y;
        g_newxyz[i * 3 + 2] = z;
        float* o = out + ((size_t)b * 1025 + 1 + s) * 3;
        o[0] = x; o[1] = y; o[2] = z;
        if (s == 0) {
            const float* c = xyz + (size_t)b * NTOT * 3;
            float* oc = out + (size_t)b * 1025 * 3;
            oc[0] = c[0]; oc[1] = c[1]; oc[2] = c[2];
        }
    }
}

// ---------------------------------------------------------------------------
// kNN-16 v3: 32 queries/CTA (block=128, 4 threads/query), packed f32x2
// distance math over SoA pair tiles. d2 = fma(dot2, -2, qn+pn): exact because
// 2*dot is a power-of-2 scale (no rounding), so single-rounded fma == ref's
// mul-then-sub. Register heap of u64 keys (ord(d2)<<32|idx); strict d2<wv
// with ascending idx per thread == exact lexicographic (d2, idx) retention.
// ---------------------------------------------------------------------------
#define QPB   32                   // queries per block
#define KTILE 1024                 // candidates per tile
__global__ void __launch_bounds__(128) knn_kernel(const float* __restrict__ xyz) {
    __shared__ ull s_x2[KTILE / 2], s_y2[KTILE / 2], s_z2[KTILE / 2], s_n2[KTILE / 2];
    __shared__ ull s_mr[QPB][65];

    int t = threadIdx.x;
    int q = t >> 2;            // query within block
    int sub = t & 3;           // pair subset
    int srow = blockIdx.x * QPB + q;   // global sample row (b*1024+s)
    int b = srow >> 10;

    float qx = g_newxyz[srow * 3 + 0];
    float qy = g_newxyz[srow * 3 + 1];
    float qz = g_newxyz[srow * 3 + 2];
    float qn = __fadd_rn(__fadd_rn(__fmul_rn(qx, qx), __fmul_rn(qy, qy)), __fmul_rn(qz, qz));
    ull qx2, qy2, qz2, qn2, n2two;
    PACKDUP(qx2, qx); PACKDUP(qy2, qy); PACKDUP(qz2, qz); PACKDUP(qn2, qn);
    PACKDUP(n2two, -2.0f);

    // heap: 16 packed keys; unique +inf sentinels (evicted largest-first)
    ull h[16];
#pragma unroll
    for (int k = 0; k < 16; k++)
        h[k] = (0xFF800000ull << 32) | (0xFFFFFFF0u + (unsigned)k);
    ull wkey = h[15];
    float wv = __int_as_float(0x7f800000);           // +inf

    const float* base = xyz + ((size_t)b * NTOT + 1) * 3;
    for (int tile = 0; tile < NR; tile += KTILE) {
        __syncthreads();
        for (int e = t; e < KTILE / 2; e += 128) {
            int p = tile + 2 * e;
            const float* g = base + (size_t)p * 3;
            float x0 = g[0], y0 = g[1], z0 = g[2];
            float x1 = g[3], y1 = g[4], z1 = g[5];
            ull x2, y2, z2;
            PACK2(x2, x0, x1); PACK2(y2, y0, y1); PACK2(z2, z0, z1);
            ull a, bq, c, s1, n2;
            MUL2(a, x2, x2); MUL2(bq, y2, y2); MUL2(c, z2, z2);
            ADD2(s1, a, bq); ADD2(n2, s1, c);
            s_x2[e] = x2; s_y2[e] = y2; s_z2[e] = z2; s_n2[e] = n2;
        }
        __syncthreads();
#pragma unroll 4
        for (int w = 0; w < KTILE / 8; w++) {
            int jj = w * 4 + sub;
            ull cx = s_x2[jj], cy = s_y2[jj], cz = s_z2[jj], cn = s_n2[jj];
            ull m1, m2, m3, a1, dot2, s2, d2p;
            MUL2(m1, qx2, cx);
            MUL2(m2, qy2, cy);
            MUL2(m3, qz2, cz);
            ADD2(a1, m1, m2);
            ADD2(dot2, a1, m3);
            ADD2(s2, qn2, cn);
            FFMA2N(d2p, dot2, n2two, s2);
            float d0, d1;
            UNPACK2(d0, d1, d2p);
            int idx0 = tile + 2 * jj;
            if (d0 < wv) {
                unsigned ub = __float_as_uint(d0);
                ub = ((int)ub < 0) ? ~ub : (ub | 0x80000000u);
                ull key = ((ull)ub << 32) | (unsigned)idx0;
#pragma unroll
                for (int k = 0; k < 16; k++) h[k] = (h[k] == wkey) ? key : h[k];
                wkey = h[0];
#pragma unroll
                for (int k = 1; k < 16; k++) wkey = (h[k] > wkey) ? h[k] : wkey;
                unsigned hi = (unsigned)(wkey >> 32);
                wv = __uint_as_float((hi & 0x80000000u) ? (hi & 0x7fffffffu) : ~hi);
            }
            if (d1 < wv) {
                unsigned ub = __float_as_uint(d1);
                ub = ((int)ub < 0) ? ~ub : (ub | 0x80000000u);
                ull key = ((ull)ub << 32) | (unsigned)(idx0 + 1);
#pragma unroll
                for (int k = 0; k < 16; k++) h[k] = (h[k] == wkey) ? key : h[k];
                wkey = h[0];
#pragma unroll
                for (int k = 1; k < 16; k++) wkey = (h[k] > wkey) ? h[k] : wkey;
                unsigned hi = (unsigned)(wkey >> 32);
                wv = __uint_as_float((hi & 0x80000000u) ? (hi & 0x7fffffffu) : ~hi);
            }
        }
    }

    // dump per-thread heaps, merge 64 -> 16 per query
#pragma unroll
    for (int k = 0; k < 16; k++) s_mr[q][sub * 16 + k] = h[k];
    __syncthreads();
    if (sub == 0) {
        ull* row = s_mr[q];
        int* dst = g_knn + (size_t)srow * NS;
        for (int k = 0; k < 16; k++) {
            ull best = ~0ull; int bj = 0;
            for (int j = 0; j < 64; j++) {
                ull v = row[j];
                if (v < best) { best = v; bj = j; }
            }
            dst[k] = (int)(best & 0xffffffffu);
            row[bj] = ~0ull;
        }
    }
}

// ---------------------------------------------------------------------------
// Layer 0: gathered feat(64) @ W0t -> bn+relu -> g_y0. 128x128 tile, k-chunk 16.
// B pre-duplicated u64 in smem (conflict-free at o=16j+tx); A as row-pair u64.
// ---------------------------------------------------------------------------
__global__ void __launch_bounds__(256) l0_kernel(const float* __restrict__ xyz,
                                                 const float* __restrict__ points) {
    __shared__ __align__(16) float As[16][134];
    __shared__ ull Bs2[16][128];
    __shared__ int   s_n[128];
    __shared__ float s_nx[8][3];

    int ct = blockIdx.x;
    int sbase = ct * 8;
    int b = sbase >> 10;
    int t = threadIdx.x;
    int tx = t & 15, ty = t >> 4;

    if (t < 128) s_n[t] = g_knn[(size_t)(sbase + (t >> 4)) * NS + (t & 15)];
    if (t < 24)  s_nx[t / 3][t % 3] = g_newxyz[(sbase + t / 3) * 3 + (t % 3)];
    __syncthreads();

    ull acc2[4][8];
#pragma unroll
    for (int i = 0; i < 4; i++)
#pragma unroll
        for (int j = 0; j < 8; j++) acc2[i][j] = 0ull;

    for (int kc = 0; kc < 64; kc += 16) {
        for (int e = t; e < 16 * 128; e += 256) {
            int k = e >> 7, o = e & 127;
            float w = g_w0t[(kc + k) * 128 + o];
            ull wd; PACKDUP(wd, w);
            Bs2[k][o] = wd;
        }
        for (int e = t; e < 128 * 16; e += 256) {
            int r = e >> 4, k = e & 15;
            int kk = kc + k;
            int n = s_n[r];
            float v;
            if (kk < 3) {
                v = __fsub_rn(xyz[((size_t)b * NTOT + 1 + n) * 3 + kk], s_nx[r >> 4][kk]);
            } else {
                v = points[((size_t)b * NTOT + 1 + n) * DPT + (kk - 3)];
            }
            As[k][r] = v;
        }
        __syncthreads();
#pragma unroll
        for (int k = 0; k < 16; k++) {
            ull a2[4], b2[8];
#pragma unroll
            for (int i = 0; i < 4; i++)
                a2[i] = *reinterpret_cast<const ull*>(&As[k][ty * 8 + 2 * i]);
#pragma unroll
            for (int j = 0; j < 8; j++) b2[j] = Bs2[k][16 * j + tx];
#pragma unroll
            for (int i = 0; i < 4; i++)
#pragma unroll
                for (int j = 0; j < 8; j++) FFMA2(acc2[i][j], a2[i], b2[j]);
        }
        __syncthreads();
    }

#pragma unroll
    for (int i = 0; i < 4; i++) {
        int r0 = ty * 8 + 2 * i;
        size_t row0 = (size_t)sbase * 16 + r0;
#pragma unroll
        for (int j = 0; j < 8; j++) {
            float lo, hiv;
            UNPACK2(lo, hiv, acc2[i][j]);
            int o = 16 * j + tx;
            float A = g_A0[o], Bv = g_B0[o];
            g_y0[row0 * CH + o]        = fmaxf(lo  * A + Bv, 0.0f);
            g_y0[(row0 + 1) * CH + o]  = fmaxf(hiv * A + Bv, 0.0f);
        }
    }
}

// ---------------------------------------------------------------------------
// Layer 1: g_y0(128) @ W1t -> bn+relu -> maxpool(16) -> out_pts.
// ---------------------------------------------------------------------------
__global__ void __launch_bounds__(256) l1_kernel(float* __restrict__ out) {
    __shared__ __align__(16) float As[16][134];
    __shared__ ull Bs2[16][128];
    __shared__ float sRed[16][128];

    int ct = blockIdx.x;
    int sbase = ct * 8;
    int t = threadIdx.x;
    int tx = t & 15, ty = t >> 4;

    ull acc2[4][8];
#pragma unroll
    for (int i = 0; i < 4; i++)
#pragma unroll
        for (int j = 0; j < 8; j++) acc2[i][j] = 0ull;

    for (int kc = 0; kc < 128; kc += 16) {
        for (int e = t; e < 16 * 128; e += 256) {
            int k = e >> 7, o = e & 127;
            float w = g_w1t[(kc + k) * 128 + o];
            ull wd; PACKDUP(wd, w);
            Bs2[k][o] = wd;
        }
        for (int e = t; e < 128 * 16; e += 256) {
            int r = e >> 4, k = e & 15;
            As[k][r] = g_y0[((size_t)sbase * 16 + r) * CH + kc + k];
        }
        __syncthreads();
#pragma unroll
        for (int k = 0; k < 16; k++) {
            ull a2[4], b2[8];
#pragma unroll
            for (int i = 0; i < 4; i++)
                a2[i] = *reinterpret_cast<const ull*>(&As[k][ty * 8 + 2 * i]);
#pragma unroll
            for (int j = 0; j < 8; j++) b2[j] = Bs2[k][16 * j + tx];
#pragma unroll
            for (int i = 0; i < 4; i++)
#pragma unroll
                for (int j = 0; j < 8; j++) FFMA2(acc2[i][j], a2[i], b2[j]);
        }
        __syncthreads();
    }

    // bn+relu then per-thread max over its 8 rows (half-sample)
#pragma unroll
    for (int j = 0; j < 8; j++) {
        int o = 16 * j + tx;
        float A = g_A1[o], Bv = g_B1[o];
        float mm = -1e30f;
#pragma unroll
        for (int i = 0; i < 4; i++) {
            float lo, hiv;
            UNPACK2(lo, hiv, acc2[i][j]);
            mm = fmaxf(mm, fmaxf(lo  * A + Bv, 0.0f));
            mm = fmaxf(mm, fmaxf(hiv * A + Bv, 0.0f));
        }
        sRed[ty][o] = mm;
    }
    __syncthreads();

    for (int e = t; e < 8 * 128; e += 256) {
        int sl = e >> 7, o = e & 127;
        float v = fmaxf(sRed[2 * sl][o], sRed[2 * sl + 1][o]);
        int srow = sbase + sl;
        int bb2 = srow >> 10, ss = srow & 1023;
        out[OXYZ + ((size_t)bb2 * 1025 + 1 + ss) * CH + o] = v;
    }
}

// ---------------------------------------------------------------------------
// cls token branch
// ---------------------------------------------------------------------------
__global__ void __launch_bounds__(128) cls_kernel(
    const float* __restrict__ xyz, const float* __restrict__ points,
    const float* __restrict__ w0, const float* __restrict__ b0,
    const float* __restrict__ g0, const float* __restrict__ bt0,
    const float* __restrict__ m0, const float* __restrict__ v0,
    const float* __restrict__ w1, const float* __restrict__ b1,
    const float* __restrict__ g1, const float* __restrict__ bt1,
    const float* __restrict__ m1, const float* __restrict__ v1,
    float* __restrict__ out) {
    int b = blockIdx.x, t = threadIdx.x;
    __shared__ float fin[64], h0[128];
    if (t < 3)            fin[t] = xyz[(size_t)b * NTOT * 3 + t];
    if (t >= 3 && t < 64) fin[t] = points[(size_t)b * NTOT * DPT + (t - 3)];
    __syncthreads();

    float acc = 0.0f;
    for (int c = 0; c < 64; c++) acc += fin[c] * w0[t * 64 + c];
    float y = (acc + b0[t] - m0[t]) * g0[t] / sqrtf(v0[t] + EPSV) + bt0[t];
    h0[t] = fmaxf(y, 0.0f);
    __syncthreads();

    acc = 0.0f;
    for (int c = 0; c < 128; c++) acc += h0[c] * w1[t * 128 + c];
    y = (acc + b1[t] - m1[t]) * g1[t] / sqrtf(v1[t] + EPSV) + bt1[t];
    out[OXYZ + (size_t)b * 1025 * CH + t] = fmaxf(y, 0.0f);
}

// ---------------------------------------------------------------------------
// launch
// ---------------------------------------------------------------------------
extern "C" void kernel_launch(void* const* d_in, const int* in_sizes, int n_in,
                              void* d_out, int out_size) {
    const float* xyz    = (const float*)d_in[0];
    const float* points = (const float*)d_in[1];
    const float* sa_w0  = (const float*)d_in[2];
    const float* sa_b0  = (const float*)d_in[3];
    const float* sa_g0  = (const float*)d_in[4];
    const float* sa_bt0 = (const float*)d_in[5];
    const float* sa_m0  = (const float*)d_in[6];
    const float* sa_v0  = (const float*)d_in[7];
    const float* cl_w0  = (const float*)d_in[8];
    const float* cl_b0  = (const float*)d_in[9];
    const float* cl_g0  = (const float*)d_in[10];
    const float* cl_bt0 = (const float*)d_in[11];
    const float* cl_m0  = (const float*)d_in[12];
    const float* cl_v0  = (const float*)d_in[13];
    const float* sa_w1  = (const float*)d_in[14];
    const float* sa_b1  = (const float*)d_in[15];
    const float* sa_g1  = (const float*)d_in[16];
    const float* sa_bt1 = (const float*)d_in[17];
    const float* sa_m1  = (const float*)d_in[18];
    const float* sa_v1  = (const float*)d_in[19];
    const float* cl_w1  = (const float*)d_in[20];
    const float* cl_b1  = (const float*)d_in[21];
    const float* cl_g1  = (const float*)d_in[22];
    const float* cl_bt1 = (const float*)d_in[23];
    const float* cl_m1  = (const float*)d_in[24];
    const float* cl_v1  = (const float*)d_in[25];
    float* out = (float*)d_out;

    static bool attr_set = false;
    if (!attr_set) {
        cudaFuncSetAttribute(fps_kernel, cudaFuncAttributeMaxDynamicSharedMemorySize,
                             NR * 3 * sizeof(float));
        attr_set = true;
    }

    prep_kernel<<<1, 256>>>(sa_w0, sa_b0, sa_g0, sa_bt0, sa_m0, sa_v0,
                            sa_w1, sa_b1, sa_g1, sa_bt1, sa_m1, sa_v1);
    fps_kernel<<<BATCH, 256, NR * 3 * sizeof(float)>>>(xyz);
    newxyz_kernel<<<(BATCH * NP + 255) / 256, 256>>>(xyz, out);
    knn_kernel<<<BATCH * NP / QPB, 128>>>(xyz);
    l0_kernel<<<BATCH * NP / 8, 256>>>(xyz, points);
    l1_kernel<<<BATCH * NP / 8, 256>>>(out);
    cls_kernel<<<BATCH, 128>>>(xyz, points,
                               cl_w0, cl_b0, cl_g0, cl_bt0, cl_m0, cl_v0,
                               cl_w1, cl_b1, cl_g1, cl_bt1, cl_m1, cl_v1,
                               out);
}

// round 7
// speedup vs baseline: 2.2301x; 1.0104x over previous
#include <cuda_runtime.h>
#include <math.h>

#define BATCH   8
#define NTOT    4097
#define NR      4096
#define DPT     61
#define NP      1024
#define NS      16
#define CH      128
#define EPSV    1e-5f
#define OXYZ    (BATCH*1025*3)   // offset of out_pts in flattened output

typedef unsigned long long ull;

// ----------------------------- device scratch ------------------------------
__device__ int   g_fid[BATCH * NP];
__device__ float g_newxyz[BATCH * NP * 3];
__device__ int   g_knn[BATCH * NP * NS];
__device__ float g_y0[(size_t)BATCH * NP * NS * CH];   // 64 MB
__device__ __align__(16) float g_w0t[64 * CH];          // [cin][cout]
__device__ __align__(16) float g_w1t[CH * CH];          // [cin][cout]
__device__ __align__(16) float g_A0[CH];
__device__ __align__(16) float g_B0[CH];
__device__ __align__(16) float g_A1[CH];
__device__ __align__(16) float g_B1[CH];

// packed f32x2 helpers (sm_103a): ptxas only emits packed math from explicit PTX
#define PACKDUP(dst, s) do { unsigned _u = __float_as_uint(s); \
    asm("mov.b64 %0, {%1, %1};" : "=l"(dst) : "r"(_u)); } while (0)
#define PACK2(dst, lo, hi) \
    asm("mov.b64 %0, {%1, %2};" : "=l"(dst) : "f"(lo), "f"(hi))
#define FFMA2(acc, a, b) \
    asm("fma.rn.f32x2 %0, %1, %2, %0;" : "+l"(acc) : "l"(a), "l"(b))
#define FFMA2N(dst, a, b, c) \
    asm("fma.rn.f32x2 %0, %1, %2, %3;" : "=l"(dst) : "l"(a), "l"(b), "l"(c))
#define ADD2(dst, a, b) \
    asm("add.rn.f32x2 %0, %1, %2;" : "=l"(dst) : "l"(a), "l"(b))
#define MUL2(dst, a, b) \
    asm("mul.rn.f32x2 %0, %1, %2;" : "=l"(dst) : "l"(a), "l"(b))
#define UNPACK2(lo, hi, v) \
    asm("mov.b64 {%0, %1}, %2;" : "=f"(lo), "=f"(hi) : "l"(v))

// ---------------------------------------------------------------------------
// prep: transpose SA weights, fold BN:  bn(Wx+b) = (Wx)*A + B
// ---------------------------------------------------------------------------
__global__ void prep_kernel(const float* __restrict__ w0, const float* __restrict__ b0,
                            const float* __restrict__ g0, const float* __restrict__ bt0,
                            const float* __restrict__ m0, const float* __restrict__ v0,
                            const float* __restrict__ w1, const float* __restrict__ b1,
                            const float* __restrict__ g1, const float* __restrict__ bt1,
                            const float* __restrict__ m1, const float* __restrict__ v1) {
    int t = threadIdx.x;
    for (int i = t; i < 64 * CH; i += 256) {
        int c = i >> 7, o = i & 127;
        g_w0t[i] = w0[o * 64 + c];
    }
    for (int i = t; i < CH * CH; i += 256) {
        int c = i >> 7, o = i & 127;
        g_w1t[i] = w1[o * CH + c];
    }
    if (t < CH) {
        float a0 = g0[t] / sqrtf(v0[t] + EPSV);
        g_A0[t] = a0;
        g_B0[t] = (b0[t] - m0[t]) * a0 + bt0[t];
        float a1 = g1[t] / sqrtf(v1[t] + EPSV);
        g_A1[t] = a1;
        g_B1[t] = (b1[t] - m1[t]) * a1 + bt1[t];
    }
}

// ---------------------------------------------------------------------------
// FPS: one CTA/batch, 256 threads * 16 pts (8 packed pairs). Exact reference
// arithmetic. One barrier/iter; shortened per-iteration latency chain:
// fmax tree + FSETP-mask argpick + packed u64 level-2 broadcast reduce.
// ---------------------------------------------------------------------------
__global__ void __launch_bounds__(256) fps_kernel(const float* __restrict__ xyz) {
    extern __shared__ float sh[];
    float* s_x = sh;            // [4096]
    float* s_y = sh + NR;       // [4096]
    float* s_z = sh + 2 * NR;   // [4096]
    __shared__ ull s_key[2][8];

    int b = blockIdx.x;
    int tid = threadIdx.x;
    int lane = tid & 31;
    int wid = tid >> 5;
    const float* base = xyz + ((size_t)b * NTOT + 1) * 3;

    for (int i = tid; i < NR * 3; i += 256) {
        float v = base[i];
        int p = i / 3, c = i - 3 * p;
        if (c == 0) s_x[p] = v; else if (c == 1) s_y[p] = v; else s_z[p] = v;
    }
    __syncthreads();

    int p0 = tid * 16;
    ull px2[8], py2[8], pz2[8];
    float dd[16];
#pragma unroll
    for (int j = 0; j < 8; j++) {
        int p = p0 + 2 * j;
        PACK2(px2[j], s_x[p], s_x[p + 1]);
        PACK2(py2[j], s_y[p], s_y[p + 1]);
        PACK2(pz2[j], s_z[p], s_z[p + 1]);
        dd[2 * j] = 1e10f; dd[2 * j + 1] = 1e10f;
    }

    int far = 0;
    for (int it = 0; it < NP; it++) {
        if (tid == 0) g_fid[b * NP + it] = far;
        float cx = s_x[far], cy = s_y[far], cz = s_z[far];
        ull ncx2, ncy2, ncz2;
        PACKDUP(ncx2, -cx); PACKDUP(ncy2, -cy); PACKDUP(ncz2, -cz);

        float u[8];
#pragma unroll
        for (int j = 0; j < 8; j++) {
            ull dx2, dy2, dz2, m1, m2, m3, s1, d2p;
            ADD2(dx2, px2[j], ncx2);
            ADD2(dy2, py2[j], ncy2);
            ADD2(dz2, pz2[j], ncz2);
            MUL2(m1, dx2, dx2);
            MUL2(m2, dy2, dy2);
            MUL2(m3, dz2, dz2);
            ADD2(s1, m1, m2);
            ADD2(d2p, s1, m3);
            float d0, d1;
            UNPACK2(d0, d1, d2p);
            dd[2 * j]     = fminf(dd[2 * j], d0);
            dd[2 * j + 1] = fminf(dd[2 * j + 1], d1);
            u[j] = fmaxf(dd[2 * j], dd[2 * j + 1]);
        }
        // tree max
        float v0 = fmaxf(u[0], u[1]), v1 = fmaxf(u[2], u[3]);
        float v2 = fmaxf(u[4], u[5]), v3 = fmaxf(u[6], u[7]);
        float w0 = fmaxf(v0, v1), w1 = fmaxf(v2, v3);
        float tm = fmaxf(w0, w1);
        // first local index achieving tm: predicate mask + ffs
        unsigned msk = 0;
#pragma unroll
        for (int i = 0; i < 16; i++) msk |= (dd[i] == tm) ? (1u << i) : 0u;
        int bi = p0 + (__ffs(msk) - 1);

        unsigned ub = __float_as_uint(tm);                     // dd >= 0: bit-monotonic
        unsigned m  = __reduce_max_sync(0xffffffffu, ub);
        unsigned cd = (ub == m) ? (unsigned)bi : 0xffffffffu;  // first-index tiebreak
        unsigned wi = __reduce_min_sync(0xffffffffu, cd);

        int pb = it & 1;
        if (lane == 0)
            s_key[pb][wid] = ((ull)m << 32) | (unsigned)(4095 - (int)wi);
        __syncthreads();
        // level-2: broadcast 8 keys, register max tree (max val, tie -> min idx)
        ull k0 = s_key[pb][0], k1 = s_key[pb][1], k2 = s_key[pb][2], k3 = s_key[pb][3];
        ull k4 = s_key[pb][4], k5 = s_key[pb][5], k6 = s_key[pb][6], k7 = s_key[pb][7];
        ull a0 = k0 > k1 ? k0 : k1, a1 = k2 > k3 ? k2 : k3;
        ull a2 = k4 > k5 ? k4 : k5, a3 = k6 > k7 ? k6 : k7;
        ull b0 = a0 > a1 ? a0 : a1, b1 = a2 > a3 ? a2 : a3;
        ull best = b0 > b1 ? b0 : b1;
        far = 4095 - (int)(best & 0xffffffffu);
    }
}

// ---------------------------------------------------------------------------
// new_xyz gather + out_xyz write
// ---------------------------------------------------------------------------
__global__ void newxyz_kernel(const float* __restrict__ xyz, float* __restrict__ out) {
    int i = blockIdx.x * 256 + threadIdx.x;
    if (i < BATCH * NP) {
        int b = i >> 10, s = i & 1023;
        int f = g_fid[i];
        const float* q = xyz + ((size_t)b * NTOT + 1 + f) * 3;
        float x = q[0], y = q[1], z = q[2];
        g_newxyz[i * 3 + 0] = x;
        g_newxyz[i * 3 + 1] = y;
        g_newxyz[i * 3 + 2] = z;
        float* o = out + ((size_t)b * 1025 + 1 + s) * 3;
        o[0] = x; o[1] = y; o[2] = z;
        if (s == 0) {
            const float* c = xyz + (size_t)b * NTOT * 3;
            float* oc = out + (size_t)b * 1025 * 3;
            oc[0] = c[0]; oc[1] = c[1]; oc[2] = c[2];
        }
    }
}

// ---------------------------------------------------------------------------
// kNN-16 v4: 16 queries/CTA, 8 threads/query (block=128, grid=512).
// Packed f32x2 distance math; per-thread top-16 kept as a binary MAX-heap of
// u64 keys (ord(d2)<<32|idx) in smem: insert = root-replace + 4-level
// branchless sift (~55 instr, mixed pipes) instead of 124-instr rescan.
// Merge 8x16 -> 16 smallest via shfl(width=8) tournament = stable top_k.
// ---------------------------------------------------------------------------
#define QPB   16                   // queries per block
#define KTILE 1024                 // candidates per tile

__device__ __forceinline__ float unord_f(unsigned hi) {
    return __uint_as_float((hi & 0x80000000u) ? (hi ^ 0x80000000u) : ~hi);
}

__device__ __forceinline__ void heap_insert(ull* Hc, ull key, ull& wkey, float& wv) {
    int pos = 0;
    ull newroot = key;
#pragma unroll
    for (int lvl = 0; lvl < 4; lvl++) {
        int c1 = 2 * pos + 1, c2 = c1 + 1;
        ull k1, k2;
        if (lvl == 3) {
            k1 = (c1 < 16) ? Hc[c1 * 128] : 0ull;
            k2 = (c2 < 16) ? Hc[c2 * 128] : 0ull;
        } else {
            k1 = Hc[c1 * 128];
            k2 = Hc[c2 * 128];
        }
        ull kc = (k1 >= k2) ? k1 : k2;
        int cc = (k1 >= k2) ? c1 : c2;
        if (kc > key) {
            Hc[pos * 128] = kc;
            if (lvl == 0) newroot = kc;
            pos = cc;
        }
    }
    Hc[pos * 128] = key;
    wkey = newroot;
    wv = unord_f((unsigned)(newroot >> 32));
}

__global__ void __launch_bounds__(128) knn_kernel(const float* __restrict__ xyz) {
    __shared__ ull s_x2[KTILE / 2], s_y2[KTILE / 2], s_z2[KTILE / 2], s_n2[KTILE / 2];
    __shared__ ull s_h[16 * 128];

    int t = threadIdx.x;
    int q = t >> 3;            // query within block (0..15)
    int sub = t & 7;           // candidate subset (0..7)
    int srow = blockIdx.x * QPB + q;   // global sample row (b*1024+s)
    int b = srow >> 10;
    ull* Hc = s_h + t;

    float qx = g_newxyz[srow * 3 + 0];
    float qy = g_newxyz[srow * 3 + 1];
    float qz = g_newxyz[srow * 3 + 2];
    float qn = __fadd_rn(__fadd_rn(__fmul_rn(qx, qx), __fmul_rn(qy, qy)), __fmul_rn(qz, qz));
    ull qx2, qy2, qz2, qn2, n2two;
    PACKDUP(qx2, qx); PACKDUP(qy2, qy); PACKDUP(qz2, qz); PACKDUP(qn2, qn);
    PACKDUP(n2two, -2.0f);

    // heap init: descending sentinels satisfy max-heap property; root = worst
#pragma unroll
    for (int k = 0; k < 16; k++)
        Hc[k * 128] = (0xFF800000ull << 32) | (0xFFFFFFFFu - (unsigned)k);
    ull wkey = (0xFF800000ull << 32) | 0xFFFFFFFFu;
    float wv = __int_as_float(0x7f800000);           // +inf

    const float* base = xyz + ((size_t)b * NTOT + 1) * 3;
    for (int tile = 0; tile < NR; tile += KTILE) {
        __syncthreads();
        for (int e = t; e < KTILE / 2; e += 128) {
            int p = tile + 2 * e;
            const float* g = base + (size_t)p * 3;
            float x0 = g[0], y0 = g[1], z0 = g[2];
            float x1 = g[3], y1 = g[4], z1 = g[5];
            ull x2, y2, z2;
            PACK2(x2, x0, x1); PACK2(y2, y0, y1); PACK2(z2, z0, z1);
            ull a, bq, c, s1, n2;
            MUL2(a, x2, x2); MUL2(bq, y2, y2); MUL2(c, z2, z2);
            ADD2(s1, a, bq); ADD2(n2, s1, c);
            s_x2[e] = x2; s_y2[e] = y2; s_z2[e] = z2; s_n2[e] = n2;
        }
        __syncthreads();
#pragma unroll 2
        for (int w = 0; w < KTILE / 16; w++) {
            int jj = w * 8 + sub;
            ull cx = s_x2[jj], cy = s_y2[jj], cz = s_z2[jj], cn = s_n2[jj];
            ull m1, m2, m3, a1, dot2, s2, d2p;
            MUL2(m1, qx2, cx);
            MUL2(m2, qy2, cy);
            MUL2(m3, qz2, cz);
            ADD2(a1, m1, m2);
            ADD2(dot2, a1, m3);
            ADD2(s2, qn2, cn);
            FFMA2N(d2p, dot2, n2two, s2);     // exact: 2*dot is exact scale
            float d0, d1;
            UNPACK2(d0, d1, d2p);
            int idx0 = tile + 2 * jj;
            if (d0 < wv) {
                unsigned ub = __float_as_uint(d0);
                ub = ((int)ub < 0) ? ~ub : (ub | 0x80000000u);
                heap_insert(Hc, ((ull)ub << 32) | (unsigned)idx0, wkey, wv);
            }
            if (d1 < wv) {
                unsigned ub = __float_as_uint(d1);
                ub = ((int)ub < 0) ? ~ub : (ub | 0x80000000u);
                heap_insert(Hc, ((ull)ub << 32) | (unsigned)(idx0 + 1), wkey, wv);
            }
        }
    }

    // merge: 16 rounds of 8-lane tournament (keys unique; ~0ull = removed)
    ull mn = Hc[0]; int ms = 0;
#pragma unroll
    for (int k = 1; k < 16; k++) {
        ull v = Hc[k * 128];
        if (v < mn) { mn = v; ms = k; }
    }
    int* dst = g_knn + (size_t)srow * NS;
    for (int r = 0; r < 16; r++) {
        ull g = mn;
#pragma unroll
        for (int d = 4; d; d >>= 1) {
            ull o = __shfl_xor_sync(0xffffffffu, g, d, 8);
            g = (o < g) ? o : g;
        }
        if (sub == 0) dst[r] = (int)(g & 0xffffffffu);
        if (mn == g) {
            Hc[ms * 128] = ~0ull;
            mn = Hc[0]; ms = 0;
#pragma unroll
            for (int k = 1; k < 16; k++) {
                ull v = Hc[k * 128];
                if (v < mn) { mn = v; ms = k; }
            }
        }
    }
}

// ---------------------------------------------------------------------------
// Layer 0: gathered feat(64) @ W0t -> bn+relu -> g_y0. 128x128 tile, k-chunk 16.
// B as plain f32 pairs (32B/lane/k), A broadcast + dup'd on the fly.
// ---------------------------------------------------------------------------
__global__ void __launch_bounds__(256) l0_kernel(const float* __restrict__ xyz,
                                                 const float* __restrict__ points) {
    __shared__ __align__(16) float As[16][136];
    __shared__ ull Bs2[16][64];
    __shared__ int   s_n[128];
    __shared__ float s_nx[8][3];

    int ct = blockIdx.x;
    int sbase = ct * 8;
    int b = sbase >> 10;
    int t = threadIdx.x;
    int tx = t & 15, ty = t >> 4;

    if (t < 128) s_n[t] = g_knn[(size_t)(sbase + (t >> 4)) * NS + (t & 15)];
    if (t < 24)  s_nx[t / 3][t % 3] = g_newxyz[(sbase + t / 3) * 3 + (t % 3)];
    __syncthreads();

    ull acc2[8][4];
#pragma unroll
    for (int i = 0; i < 8; i++)
#pragma unroll
        for (int j = 0; j < 4; j++) acc2[i][j] = 0ull;

    for (int kc = 0; kc < 64; kc += 16) {
        for (int e = t; e < 16 * 64; e += 256) {
            int k = e >> 6, n = e & 63;
            const float* wp = &g_w0t[(kc + k) * 128 + 2 * n];
            ull w2; PACK2(w2, wp[0], wp[1]);
            Bs2[k][n] = w2;
        }
        for (int e = t; e < 128 * 16; e += 256) {
            int r = e >> 4, k = e & 15;
            int kk = kc + k;
            int n = s_n[r];
            float v;
            if (kk < 3) {
                v = __fsub_rn(xyz[((size_t)b * NTOT + 1 + n) * 3 + kk], s_nx[r >> 4][kk]);
            } else {
                v = points[((size_t)b * NTOT + 1 + n) * DPT + (kk - 3)];
            }
            As[k][r] = v;
        }
        __syncthreads();
#pragma unroll
        for (int k = 0; k < 16; k++) {
            ull b2[4];
#pragma unroll
            for (int j = 0; j < 4; j++) b2[j] = Bs2[k][16 * j + tx];
#pragma unroll
            for (int i = 0; i < 4; i++) {
                ull a01 = *reinterpret_cast<const ull*>(&As[k][ty * 8 + 2 * i]);
                float alo, ahi;
                UNPACK2(alo, ahi, a01);
                ull ad0, ad1;
                PACKDUP(ad0, alo); PACKDUP(ad1, ahi);
#pragma unroll
                for (int j = 0; j < 4; j++) {
                    FFMA2(acc2[2 * i][j], ad0, b2[j]);
                    FFMA2(acc2[2 * i + 1][j], ad1, b2[j]);
                }
            }
        }
        __syncthreads();
    }

#pragma unroll
    for (int i = 0; i < 8; i++) {
        size_t row = (size_t)sbase * 16 + ty * 8 + i;
#pragma unroll
        for (int j = 0; j < 4; j++) {
            int o = 2 * (16 * j + tx);
            ull pa = *reinterpret_cast<const ull*>(&g_A0[o]);
            ull pbv = *reinterpret_cast<const ull*>(&g_B0[o]);
            ull y2; FFMA2N(y2, acc2[i][j], pa, pbv);
            float lo, hiv;
            UNPACK2(lo, hiv, y2);
            ull outp;
            PACK2(outp, fmaxf(lo, 0.0f), fmaxf(hiv, 0.0f));
            *reinterpret_cast<ull*>(&g_y0[row * CH + o]) = outp;
        }
    }
}

// ---------------------------------------------------------------------------
// Layer 1: g_y0(128) @ W1t -> bn+relu -> maxpool(16) -> out_pts.
// ---------------------------------------------------------------------------
__global__ void __launch_bounds__(256) l1_kernel(float* __restrict__ out) {
    __shared__ __align__(16) float As[16][136];
    __shared__ ull Bs2[16][64];
    __shared__ float sRed[16][128];

    int ct = blockIdx.x;
    int sbase = ct * 8;
    int t = threadIdx.x;
    int tx = t & 15, ty = t >> 4;

    ull acc2[8][4];
#pragma unroll
    for (int i = 0; i < 8; i++)
#pragma unroll
        for (int j = 0; j < 4; j++) acc2[i][j] = 0ull;

    for (int kc = 0; kc < 128; kc += 16) {
        for (int e = t; e < 16 * 64; e += 256) {
            int k = e >> 6, n = e & 63;
            const float* wp = &g_w1t[(kc + k) * 128 + 2 * n];
            ull w2; PACK2(w2, wp[0], wp[1]);
            Bs2[k][n] = w2;
        }
        for (int e = t; e < 128 * 16; e += 256) {
            int r = e >> 4, k = e & 15;
            As[k][r] = g_y0[((size_t)sbase * 16 + r) * CH + kc + k];
        }
        __syncthreads();
#pragma unroll
        for (int k = 0; k < 16; k++) {
            ull b2[4];
#pragma unroll
            for (int j = 0; j < 4; j++) b2[j] = Bs2[k][16 * j + tx];
#pragma unroll
            for (int i = 0; i < 4; i++) {
                ull a01 = *reinterpret_cast<const ull*>(&As[k][ty * 8 + 2 * i]);
                float alo, ahi;
                UNPACK2(alo, ahi, a01);
                ull ad0, ad1;
                PACKDUP(ad0, alo); PACKDUP(ad1, ahi);
#pragma unroll
                for (int j = 0; j < 4; j++) {
                    FFMA2(acc2[2 * i][j], ad0, b2[j]);
                    FFMA2(acc2[2 * i + 1][j], ad1, b2[j]);
                }
            }
        }
        __syncthreads();
    }

    // bn+relu then per-thread max over its 8 rows (half-sample)
#pragma unroll
    for (int j = 0; j < 4; j++) {
        int o = 2 * (16 * j + tx);
        ull pa = *reinterpret_cast<const ull*>(&g_A1[o]);
        ull pbv = *reinterpret_cast<const ull*>(&g_B1[o]);
        float mm0 = -1e30f, mm1 = -1e30f;
#pragma unroll
        for (int i = 0; i < 8; i++) {
            ull y2; FFMA2N(y2, acc2[i][j], pa, pbv);
            float lo, hiv;
            UNPACK2(lo, hiv, y2);
            mm0 = fmaxf(mm0, fmaxf(lo, 0.0f));
            mm1 = fmaxf(mm1, fmaxf(hiv, 0.0f));
        }
        sRed[ty][o] = mm0;
        sRed[ty][o + 1] = mm1;
    }
    __syncthreads();

    for (int e = t; e < 8 * 128; e += 256) {
        int sl = e >> 7, o = e & 127;
        float v = fmaxf(sRed[2 * sl][o], sRed[2 * sl + 1][o]);
        int srow = sbase + sl;
        int bb2 = srow >> 10, ss = srow & 1023;
        out[OXYZ + ((size_t)bb2 * 1025 + 1 + ss) * CH + o] = v;
    }
}

// ---------------------------------------------------------------------------
// cls token branch
// ---------------------------------------------------------------------------
__global__ void __launch_bounds__(128) cls_kernel(
    const float* __restrict__ xyz, const float* __restrict__ points,
    const float* __restrict__ w0, const float* __restrict__ b0,
    const float* __restrict__ g0, const float* __restrict__ bt0,
    const float* __restrict__ m0, const float* __restrict__ v0,
    const float* __restrict__ w1, const float* __restrict__ b1,
    const float* __restrict__ g1, const float* __restrict__ bt1,
    const float* __restrict__ m1, const float* __restrict__ v1,
    float* __restrict__ out) {
    int b = blockIdx.x, t = threadIdx.x;
    __shared__ float fin[64], h0[128];
    if (t < 3)            fin[t] = xyz[(size_t)b * NTOT * 3 + t];
    if (t >= 3 && t < 64) fin[t] = points[(size_t)b * NTOT * DPT + (t - 3)];
    __syncthreads();

    float acc = 0.0f;
    for (int c = 0; c < 64; c++) acc += fin[c] * w0[t * 64 + c];
    float y = (acc + b0[t] - m0[t]) * g0[t] / sqrtf(v0[t] + EPSV) + bt0[t];
    h0[t] = fmaxf(y, 0.0f);
    __syncthreads();

    acc = 0.0f;
    for (int c = 0; c < 128; c++) acc += h0[c] * w1[t * 128 + c];
    y = (acc + b1[t] - m1[t]) * g1[t] / sqrtf(v1[t] + EPSV) + bt1[t];
    out[OXYZ + (size_t)b * 1025 * CH + t] = fmaxf(y, 0.0f);
}

// ---------------------------------------------------------------------------
// launch
// ---------------------------------------------------------------------------
extern "C" void kernel_launch(void* const* d_in, const int* in_sizes, int n_in,
                              void* d_out, int out_size) {
    const float* xyz    = (const float*)d_in[0];
    const float* points = (const float*)d_in[1];
    const float* sa_w0  = (const float*)d_in[2];
    const float* sa_b0  = (const float*)d_in[3];
    const float* sa_g0  = (const float*)d_in[4];
    const float* sa_bt0 = (const float*)d_in[5];
    const float* sa_m0  = (const float*)d_in[6];
    const float* sa_v0  = (const float*)d_in[7];
    const float* cl_w0  = (const float*)d_in[8];
    const float* cl_b0  = (const float*)d_in[9];
    const float* cl_g0  = (const float*)d_in[10];
    const float* cl_bt0 = (const float*)d_in[11];
    const float* cl_m0  = (const float*)d_in[12];
    const float* cl_v0  = (const float*)d_in[13];
    const float* sa_w1  = (const float*)d_in[14];
    const float* sa_b1  = (const float*)d_in[15];
    const float* sa_g1  = (const float*)d_in[16];
    const float* sa_bt1 = (const float*)d_in[17];
    const float* sa_m1  = (const float*)d_in[18];
    const float* sa_v1  = (const float*)d_in[19];
    const float* cl_w1  = (const float*)d_in[20];
    const float* cl_b1  = (const float*)d_in[21];
    const float* cl_g1  = (const float*)d_in[22];
    const float* cl_bt1 = (const float*)d_in[23];
    const float* cl_m1  = (const float*)d_in[24];
    const float* cl_v1  = (const float*)d_in[25];
    float* out = (float*)d_out;

    static bool attr_set = false;
    if (!attr_set) {
        cudaFuncSetAttribute(fps_kernel, cudaFuncAttributeMaxDynamicSharedMemorySize,
                             NR * 3 * sizeof(float));
        attr_set = true;
    }

    prep_kernel<<<1, 256>>>(sa_w0, sa_b0, sa_g0, sa_bt0, sa_m0, sa_v0,
                            sa_w1, sa_b1, sa_g1, sa_bt1, sa_m1, sa_v1);
    fps_kernel<<<BATCH, 256, NR * 3 * sizeof(float)>>>(xyz);
    newxyz_kernel<<<(BATCH * NP + 255) / 256, 256>>>(xyz, out);
    knn_kernel<<<BATCH * NP / QPB, 128>>>(xyz);
    l0_kernel<<<BATCH * NP / 8, 256>>>(xyz, points);
    l1_kernel<<<BATCH * NP / 8, 256>>>(out);
    cls_kernel<<<BATCH, 128>>>(xyz, points,
                               cl_w0, cl_b0, cl_g0, cl_bt0, cl_m0, cl_v0,
                               cl_w1, cl_b1, cl_g1, cl_bt1, cl_m1, cl_v1,
                               out);
}